// round 1
// baseline (speedup 1.0000x reference)
#include <cuda_runtime.h>
#include <cuda_bf16.h>
#include <math.h>

// Problem constants (fixed by the reference setup)
#define BB    64
#define NN    512
#define MROWS (BB*NN)        // 32768 nodes
#define DEG   8
#define ETOT  (MROWS*DEG)    // 262144 edges
#define EB    (NN*DEG)       // 4096 edges per batch
#define HD    512            // D == H == 512
#define CC    16
#define BN_EPS 1e-5f

// ---------------- static scratch (no allocations allowed) ----------------
__device__ float g_bufA[MROWS*HD];   // z0, later reused as z2
__device__ float g_bufB[MROWS*HD];   // z1
__device__ float g_s[MROWS*CC];      // softmax assignments
__device__ int   g_deg[MROWS];       // out-degree (src counts)
__device__ int   g_counts[MROWS];    // in-degree (dst counts) for CSR
__device__ int   g_cursor[MROWS];
__device__ int   g_off[MROWS+1];
__device__ int   g_csr[ETOT];        // src lists grouped by dst

__device__ __forceinline__ float warpSum(float v) {
    #pragma unroll
    for (int o = 16; o; o >>= 1) v += __shfl_xor_sync(0xffffffffu, v, o);
    return v;
}

// ---------------- init: zero counters + output ----------------
__global__ void init_kernel(float* out) {
    int i = blockIdx.x * blockDim.x + threadIdx.x;
    if (i < MROWS) { g_counts[i] = 0; g_cursor[i] = 0; g_deg[i] = 0; }
    if (i == 0) out[0] = 0.f;
}

// ---------------- CSR build ----------------
__global__ void count_kernel(const int* __restrict__ ei) {
    int e = blockIdx.x * blockDim.x + threadIdx.x;
    if (e < ETOT) {
        atomicAdd(&g_counts[ei[ETOT + e]], 1);  // in-degree by dst
        atomicAdd(&g_deg[ei[e]], 1);            // out-degree by src (adj.sum(-1))
    }
}

__global__ void scan_kernel() {  // 1 block x 1024 threads, 32 elems each
    __shared__ int part[1024];
    int t = threadIdx.x;
    int base = t * 32;
    int local[32];
    int s = 0;
    #pragma unroll
    for (int i = 0; i < 32; i++) { local[i] = s; s += g_counts[base + i]; }
    part[t] = s;
    __syncthreads();
    for (int off = 1; off < 1024; off <<= 1) {
        int v = (t >= off) ? part[t - off] : 0;
        __syncthreads();
        part[t] += v;
        __syncthreads();
    }
    int pre = (t == 0) ? 0 : part[t - 1];
    #pragma unroll
    for (int i = 0; i < 32; i++) g_off[base + i] = pre + local[i];
    if (t == 1023) g_off[MROWS] = part[1023];
}

__global__ void fill_kernel(const int* __restrict__ ei) {
    int e = blockIdx.x * blockDim.x + threadIdx.x;
    if (e < ETOT) {
        int d = ei[ETOT + e];
        int p = atomicAdd(&g_cursor[d], 1);
        g_csr[g_off[d] + p] = ei[e];
    }
}

// ---------------- z0 = emb[x] + segment_sum(emb[x[src]], dst) ----------------
__global__ void z0_kernel(const int* __restrict__ x, const float* __restrict__ emb) {
    int n = blockIdx.x;
    int t = threadIdx.x;  // 128 threads, float4 each -> 512 floats
    const float4* emb4 = (const float4*)emb;
    float4 acc = emb4[x[n] * 128 + t];
    int e1 = g_off[n + 1];
    for (int e = g_off[n]; e < e1; e++) {
        int sx = x[g_csr[e]];
        float4 v = emb4[sx * 128 + t];
        acc.x += v.x; acc.y += v.y; acc.z += v.z; acc.w += v.w;
    }
    ((float4*)g_bufA)[n * 128 + t] = acc;
}

// ---------------- tiled fp32 GEMM with fused epilogue ----------------
// WHICH==0: C(g_bufB) = elu(bn(g_bufA @ W + bias));  WHICH==1: C(g_bufA) = elu(g_bufB @ W + bias)
template<int WHICH>
__global__ __launch_bounds__(256, 2) void gemm_kernel(
    const float* __restrict__ W, const float* __restrict__ bias,
    const float* __restrict__ gamma, const float* __restrict__ beta,
    const float* __restrict__ mean, const float* __restrict__ var)
{
    const float* __restrict__ A = (WHICH == 0) ? g_bufA : g_bufB;
    float* __restrict__ C       = (WHICH == 0) ? g_bufB : g_bufA;
    __shared__ float As[16][128];
    __shared__ float Bs[16][128];
    int tid = threadIdx.x;
    int rowBase = blockIdx.y * 128, colBase = blockIdx.x * 128;
    int tx = tid & 15, ty = tid >> 4;
    float acc[8][8] = {};

    for (int kt = 0; kt < HD; kt += 16) {
        #pragma unroll
        for (int i = 0; i < 2; i++) {
            int f = tid + i * 256;
            int r = f >> 2, c4 = (f & 3) * 4;
            float4 av = *(const float4*)&A[(rowBase + r) * HD + kt + c4];
            As[c4 + 0][r] = av.x; As[c4 + 1][r] = av.y;
            As[c4 + 2][r] = av.z; As[c4 + 3][r] = av.w;
            int br = f >> 5, bc = (f & 31) * 4;
            *(float4*)&Bs[br][bc] = *(const float4*)&W[(kt + br) * HD + colBase + bc];
        }
        __syncthreads();
        #pragma unroll
        for (int k = 0; k < 16; k++) {
            float a[8], b[8];
            *(float4*)&a[0] = *(float4*)&As[k][ty * 8];
            *(float4*)&a[4] = *(float4*)&As[k][ty * 8 + 4];
            *(float4*)&b[0] = *(float4*)&Bs[k][tx * 8];
            *(float4*)&b[4] = *(float4*)&Bs[k][tx * 8 + 4];
            #pragma unroll
            for (int i = 0; i < 8; i++)
                #pragma unroll
                for (int j = 0; j < 8; j++)
                    acc[i][j] += a[i] * b[j];
        }
        __syncthreads();
    }
    #pragma unroll
    for (int i = 0; i < 8; i++) {
        int row = rowBase + ty * 8 + i;
        #pragma unroll
        for (int j = 0; j < 8; j++) {
            int col = colBase + tx * 8 + j;
            float v = acc[i][j] + bias[col];
            if (WHICH == 0)
                v = (v - mean[col]) * rsqrtf(var[col] + BN_EPS) * gamma[col] + beta[col];
            v = v > 0.f ? v : expm1f(v);
            C[row * HD + col] = v;
        }
    }
}

// ---------------- pool: s = softmax(z2 @ pool_w + pool_b) ----------------
__global__ __launch_bounds__(256) void pool_kernel(const float* __restrict__ pw,
                                                   const float* __restrict__ pb) {
    __shared__ float pws[CC * 513];  // [c][k], padded
    __shared__ float pbs[CC];
    int tid = threadIdx.x;
    for (int i = tid; i < HD * CC; i += 256) {
        int k = i >> 4, c = i & 15;
        pws[c * 513 + k] = pw[i];
    }
    if (tid < CC) pbs[tid] = pb[tid];
    __syncthreads();
    int warp = tid >> 5, lane = tid & 31;
    int n = blockIdx.x * 8 + warp;
    const float* z = g_bufA + n * HD;
    float acc[CC] = {};
    #pragma unroll
    for (int j = 0; j < 16; j++) {
        int k = lane + 32 * j;
        float zv = z[k];
        #pragma unroll
        for (int c = 0; c < CC; c++) acc[c] += zv * pws[c * 513 + k];
    }
    #pragma unroll
    for (int c = 0; c < CC; c++) acc[c] = warpSum(acc[c]);
    float mx = -INFINITY;
    #pragma unroll
    for (int c = 0; c < CC; c++) { acc[c] += pbs[c]; mx = fmaxf(mx, acc[c]); }
    float sum = 0.f;
    #pragma unroll
    for (int c = 0; c < CC; c++) { acc[c] = expf(acc[c] - mx); sum += acc[c]; }
    float inv = 1.f / sum;
    if (lane < CC) g_s[n * CC + lane] = acc[lane] * inv;
}

// ---------------- per-batch losses ----------------
__global__ __launch_bounds__(256) void loss_kernel(const int* __restrict__ ei,
                                                   float* __restrict__ out) {
    __shared__ float ssh[NN * CC];   // 32 KB
    __shared__ float dsh[NN];
    __shared__ float wsh[CC], csh[CC];
    __shared__ float sAcc[4];        // 0: totdeg, 1: edge term, 2: ss^2 sum, 3: ortho sq
    int b = blockIdx.x, t = threadIdx.x;
    int lane = t & 31;

    for (int i = t; i < NN * CC; i += 256) ssh[i] = g_s[b * NN * CC + i];
    for (int i = t; i < NN; i += 256) dsh[i] = (float)g_deg[b * NN + i];
    if (t < CC) { wsh[t] = 0.f; csh[t] = 0.f; }
    if (t < 4) sAcc[t] = 0.f;
    __syncthreads();

    // node-wise partials: total degree, w_c = sum s*deg, cluster_size
    float wp[CC] = {}, cp[CC] = {};
    float td = 0.f;
    for (int n = t; n < NN; n += 256) {
        float d = dsh[n];
        td += d;
        #pragma unroll
        for (int c = 0; c < CC; c++) {
            float sv = ssh[n * CC + c];
            wp[c] += sv * d;
            cp[c] += sv;
        }
    }
    td = warpSum(td);
    #pragma unroll
    for (int c = 0; c < CC; c++) { wp[c] = warpSum(wp[c]); cp[c] = warpSum(cp[c]); }
    if (lane == 0) {
        atomicAdd(&sAcc[0], td);
        #pragma unroll
        for (int c = 0; c < CC; c++) { atomicAdd(&wsh[c], wp[c]); atomicAdd(&csh[c], cp[c]); }
    }

    // ss[c][k] = sum_n s[n,c]*s[n,k] (one value per thread; 256 == C*C)
    int cc = t >> 4, kk = t & 15;
    float ssv = 0.f;
    for (int n = 0; n < NN; n++) ssv += ssh[n * CC + cc] * ssh[n * CC + kk];
    float s2 = warpSum(ssv * ssv);
    if (lane == 0) atomicAdd(&sAcc[2], s2);

    // edge term: sum over this batch's edges of <s[src], s[dst]>
    const int* srcp = ei;
    const int* dstp = ei + ETOT;
    float et = 0.f;
    for (int e = b * EB + t; e < (b + 1) * EB; e += 256) {
        int sl = srcp[e] - b * NN;
        int dl = dstp[e] - b * NN;
        float d2 = 0.f;
        #pragma unroll
        for (int c = 0; c < CC; c++) d2 += ssh[sl * CC + c] * ssh[dl * CC + c];
        et += d2;
    }
    et = warpSum(et);
    if (lane == 0) atomicAdd(&sAcc[1], et);
    __syncthreads();

    // ortho: || ss/||ss||_F - I/sqrt(C) ||_F
    float fro = sqrtf(sAcc[2]);
    float dd = ssv / fro - ((cc == kk) ? 0.25f : 0.f);
    float dsq = warpSum(dd * dd);
    if (lane == 0) atomicAdd(&sAcc[3], dsq);
    __syncthreads();

    if (t == 0) {
        float m = sAcc[0] * 0.5f;
        float wsq = 0.f, cs2 = 0.f;
        #pragma unroll
        for (int c = 0; c < CC; c++) { wsq += wsh[c] * wsh[c]; cs2 += csh[c] * csh[c]; }
        float trace = sAcc[1] - wsq / (2.f * m);
        float spec = -trace / (2.f * m);
        float ortho = sqrtf(sAcc[3]);
        float cluster = sqrtf(cs2) / (float)NN * 4.f - 1.f;
        atomicAdd(out, (spec + ortho + cluster) * (1.f / (float)BB));
    }
}

// ---------------- launch ----------------
extern "C" void kernel_launch(void* const* d_in, const int* in_sizes, int n_in,
                              void* d_out, int out_size) {
    const int*   x      = (const int*)d_in[0];
    const int*   ei     = (const int*)d_in[1];
    // d_in[2] = batch (derived analytically, unused)
    const float* emb    = (const float*)d_in[3];
    const float* w1     = (const float*)d_in[4];
    const float* b1     = (const float*)d_in[5];
    const float* bn_g   = (const float*)d_in[6];
    const float* bn_b   = (const float*)d_in[7];
    const float* bn_m   = (const float*)d_in[8];
    const float* bn_v   = (const float*)d_in[9];
    const float* w2     = (const float*)d_in[10];
    const float* b2     = (const float*)d_in[11];
    const float* pool_w = (const float*)d_in[12];
    const float* pool_b = (const float*)d_in[13];
    float* out = (float*)d_out;

    init_kernel<<<(MROWS + 255) / 256, 256>>>(out);
    count_kernel<<<ETOT / 256, 256>>>(ei);
    scan_kernel<<<1, 1024>>>();
    fill_kernel<<<ETOT / 256, 256>>>(ei);
    z0_kernel<<<MROWS, 128>>>(x, emb);

    dim3 gGrid(HD / 128, MROWS / 128);
    gemm_kernel<0><<<gGrid, 256>>>(w1, b1, bn_g, bn_b, bn_m, bn_v);
    gemm_kernel<1><<<gGrid, 256>>>(w2, b2, nullptr, nullptr, nullptr, nullptr);

    pool_kernel<<<MROWS / 8, 256>>>(pool_w, pool_b);
    loss_kernel<<<BB, 256>>>(ei, out);
}

// round 4
// speedup vs baseline: 1.8703x; 1.8703x over previous
#include <cuda_runtime.h>
#include <cuda_bf16.h>
#include <math.h>
#include <stdint.h>

// Problem constants
#define BB    64
#define NN    512
#define MROWS (BB*NN)        // 32768 nodes
#define DEG   8
#define ETOT  (MROWS*DEG)    // 262144 edges
#define EB    (NN*DEG)       // 4096 edges per batch
#define HD    512            // D == H == 512
#define CC    16
#define BN_EPS 1e-5f

// ---------------- static scratch ----------------
__device__ __align__(1024) __nv_bfloat16 g_Ah[MROWS*HD];   // z0 hi
__device__ __align__(1024) __nv_bfloat16 g_Al[MROWS*HD];   // z0 lo
__device__ __align__(1024) __nv_bfloat16 g_Bh[MROWS*HD];   // z1 hi
__device__ __align__(1024) __nv_bfloat16 g_Bl[MROWS*HD];   // z1 lo
__device__ __align__(1024) float         g_z2[MROWS*HD];   // z2 fp32
__device__ __align__(1024) __nv_bfloat16 g_W1h[HD*HD], g_W1l[HD*HD];  // [n][k]
__device__ __align__(1024) __nv_bfloat16 g_W2h[HD*HD], g_W2l[HD*HD];
__device__ float g_s[MROWS*CC];
__device__ int   g_deg[MROWS];
__device__ int   g_counts[MROWS];
__device__ int   g_cursor[MROWS];
__device__ int   g_off[MROWS+1];
__device__ int   g_csr[ETOT];

__device__ __forceinline__ float warpSum(float v) {
    #pragma unroll
    for (int o = 16; o; o >>= 1) v += __shfl_xor_sync(0xffffffffu, v, o);
    return v;
}

// ---------------- PTX helpers (sm_80+ portable) ----------------
__device__ __forceinline__ uint32_t smem_u32(const void* p) {
    uint32_t a;
    asm("{ .reg .u64 t; cvta.to.shared.u64 t, %1; cvt.u32.u64 %0, t; }" : "=r"(a) : "l"(p));
    return a;
}
__device__ __forceinline__ void cp16(uint32_t dst, const void* src) {
    asm volatile("cp.async.cg.shared.global [%0], [%1], 16;\n" :: "r"(dst), "l"(src));
}
__device__ __forceinline__ void cp_commit() {
    asm volatile("cp.async.commit_group;\n" ::: "memory");
}
template<int N>
__device__ __forceinline__ void cp_wait() {
    asm volatile("cp.async.wait_group %0;\n" :: "n"(N) : "memory");
}
__device__ __forceinline__ void ldm_x4(uint32_t* r, uint32_t addr) {
    asm volatile("ldmatrix.sync.aligned.m8n8.x4.shared.b16 {%0,%1,%2,%3}, [%4];"
                 : "=r"(r[0]), "=r"(r[1]), "=r"(r[2]), "=r"(r[3]) : "r"(addr));
}
__device__ __forceinline__ void mma16816(float* d, const uint32_t* a, const uint32_t* b) {
    asm volatile("mma.sync.aligned.m16n8k16.row.col.f32.bf16.bf16.f32 "
                 "{%0,%1,%2,%3}, {%4,%5,%6,%7}, {%8,%9}, {%0,%1,%2,%3};"
                 : "+f"(d[0]), "+f"(d[1]), "+f"(d[2]), "+f"(d[3])
                 : "r"(a[0]), "r"(a[1]), "r"(a[2]), "r"(a[3]), "r"(b[0]), "r"(b[1]));
}

// ---------------- init ----------------
__global__ void init_kernel(float* out) {
    int i = blockIdx.x * blockDim.x + threadIdx.x;
    if (i < MROWS) { g_counts[i] = 0; g_cursor[i] = 0; g_deg[i] = 0; }
    if (i == 0) out[0] = 0.f;
}

// ---------------- CSR build ----------------
__global__ void count_kernel(const int* __restrict__ ei) {
    int e = blockIdx.x * blockDim.x + threadIdx.x;
    if (e < ETOT) {
        atomicAdd(&g_counts[ei[ETOT + e]], 1);
        atomicAdd(&g_deg[ei[e]], 1);
    }
}

__global__ void scan_kernel() {
    __shared__ int part[1024];
    int t = threadIdx.x;
    int base = t * 32;
    int local[32];
    int s = 0;
    #pragma unroll
    for (int i = 0; i < 32; i++) { local[i] = s; s += g_counts[base + i]; }
    part[t] = s;
    __syncthreads();
    for (int off = 1; off < 1024; off <<= 1) {
        int v = (t >= off) ? part[t - off] : 0;
        __syncthreads();
        part[t] += v;
        __syncthreads();
    }
    int pre = (t == 0) ? 0 : part[t - 1];
    #pragma unroll
    for (int i = 0; i < 32; i++) g_off[base + i] = pre + local[i];
    if (t == 1023) g_off[MROWS] = part[1023];
}

__global__ void fill_kernel(const int* __restrict__ ei) {
    int e = blockIdx.x * blockDim.x + threadIdx.x;
    if (e < ETOT) {
        int d = ei[ETOT + e];
        int p = atomicAdd(&g_cursor[d], 1);
        g_csr[g_off[d] + p] = ei[e];
    }
}

// ---------------- weight prep: transpose + bf16 split ----------------
__global__ void wprep_kernel(const float* __restrict__ w1, const float* __restrict__ w2) {
    int i = blockIdx.x * blockDim.x + threadIdx.x;  // i = k*512 + n
    int k = i >> 9, n = i & 511;
    float v1 = w1[i];
    __nv_bfloat16 h1 = __float2bfloat16_rn(v1);
    g_W1h[n * HD + k] = h1;
    g_W1l[n * HD + k] = __float2bfloat16_rn(v1 - __bfloat162float(h1));
    float v2 = w2[i];
    __nv_bfloat16 h2 = __float2bfloat16_rn(v2);
    g_W2h[n * HD + k] = h2;
    g_W2l[n * HD + k] = __float2bfloat16_rn(v2 - __bfloat162float(h2));
}

// ---------------- z0 = emb[x] + segment_sum(emb[x[src]], dst), bf16 hi/lo ----------------
__global__ void z0_kernel(const int* __restrict__ x, const float* __restrict__ emb) {
    int n = blockIdx.x;
    int t = threadIdx.x;  // 128 threads x float4
    const float4* emb4 = (const float4*)emb;
    float4 acc = emb4[x[n] * 128 + t];
    int e1 = g_off[n + 1];
    for (int e = g_off[n]; e < e1; e++) {
        int sx = x[g_csr[e]];
        float4 v = emb4[sx * 128 + t];
        acc.x += v.x; acc.y += v.y; acc.z += v.z; acc.w += v.w;
    }
    int base = n * HD + t * 4;
    __nv_bfloat16 h0 = __float2bfloat16_rn(acc.x), h1 = __float2bfloat16_rn(acc.y);
    __nv_bfloat16 h2 = __float2bfloat16_rn(acc.z), h3 = __float2bfloat16_rn(acc.w);
    *(__nv_bfloat162*)(g_Ah + base)     = __nv_bfloat162(h0, h1);
    *(__nv_bfloat162*)(g_Ah + base + 2) = __nv_bfloat162(h2, h3);
    __nv_bfloat16 l0 = __float2bfloat16_rn(acc.x - __bfloat162float(h0));
    __nv_bfloat16 l1 = __float2bfloat16_rn(acc.y - __bfloat162float(h1));
    __nv_bfloat16 l2 = __float2bfloat16_rn(acc.z - __bfloat162float(h2));
    __nv_bfloat16 l3 = __float2bfloat16_rn(acc.w - __bfloat162float(h3));
    *(__nv_bfloat162*)(g_Al + base)     = __nv_bfloat162(l0, l1);
    *(__nv_bfloat162*)(g_Al + base + 2) = __nv_bfloat162(l2, l3);
}

// ---------------- mma.sync bf16-split GEMM ----------------
// 128x128 CTA tile, 8 warps (2x4), K-chunk 64, 3-stage cp.async pipeline.
// WHICH==0: z1 = elu(bn(z0 @ w1 + b1)) -> g_Bh/g_Bl (bf16 split)
// WHICH==1: z2 = elu(z1 @ w2 + b2)     -> g_z2 (fp32)

#define STAGE_BYTES 65536          // Ah 16K | Al 16K | Bh 16K | Bl 16K
#define NSTAGE 3
#define SMEM_GEMM (NSTAGE * STAGE_BYTES)

template<int WHICH>
__global__ __launch_bounds__(256, 1) void gemm_mma(
    const float* __restrict__ bias, const float* __restrict__ gamma,
    const float* __restrict__ beta, const float* __restrict__ mean,
    const float* __restrict__ var)
{
    extern __shared__ __align__(1024) char smem[];
    const uint32_t sb = smem_u32(smem);
    const int tid = threadIdx.x;
    const int wid = tid >> 5, lane = tid & 31;
    const int wm = wid & 1;        // 0..1 -> 64 rows
    const int wn = wid >> 1;       // 0..3 -> 32 cols
    const int rowBase = blockIdx.y * 128;
    const int colBase = blockIdx.x * 128;

    const __nv_bfloat16* __restrict__ Ahp = WHICH ? g_Bh : g_Ah;
    const __nv_bfloat16* __restrict__ Alp = WHICH ? g_Bl : g_Al;
    const __nv_bfloat16* __restrict__ Whp = WHICH ? g_W2h : g_W1h;
    const __nv_bfloat16* __restrict__ Wlp = WHICH ? g_W2l : g_W1l;

    // ---- loader: 16 x 16B cp.async per thread per chunk ----
    // idx in [0,4096): quarter q (plane), row r (0..127), 16B block cc (0..7)
    auto loadChunk = [&](int c, int s) {
        const uint32_t stage = sb + s * STAGE_BYTES;
        #pragma unroll
        for (int it = 0; it < 16; it++) {
            int idx = tid + it * 256;
            int q = idx >> 10;                    // compile-time-known per it (tid<256)
            int r = (idx & 1023) >> 3;
            int cc = idx & 7;
            const __nv_bfloat16* base =
                (q == 0) ? Ahp : (q == 1) ? Alp : (q == 2) ? Whp : Wlp;
            int grow = ((q < 2) ? rowBase : colBase) + r;
            const __nv_bfloat16* src = base + (size_t)grow * HD + c * 64 + cc * 8;
            uint32_t off = r * 128 + cc * 16;
            uint32_t sw = off ^ ((off >> 3) & 0x70);
            cp16(stage + q * 16384 + sw, src);
        }
        cp_commit();
    };

    // ---- ldmatrix per-thread addressing ----
    const int g = lane >> 3;                  // 0..3 (8x8 tile index within x4)
    // A: tiles [m0-7 k0], [m8-15 k0], [m0-7 k8], [m8-15 k8]
    const int aRowL = (g & 1) * 8 + (lane & 7);
    const int aKb   = (g >> 1);               // 16B block within k16
    // B: tiles [n0-7 k0], [n0-7 k8], [n8-15 k0], [n8-15 k8]
    const int bRowL = (g >> 1) * 8 + (lane & 7);
    const int bKb   = (g & 1);

    uint32_t aRowOff[4], aXor[4];
    #pragma unroll
    for (int i = 0; i < 4; i++) {
        int ar = wm * 64 + i * 16 + aRowL;
        aRowOff[i] = ar * 128;
        aXor[i] = (ar & 7) << 4;
    }
    uint32_t bRowOff[2], bXor[2];
    #pragma unroll
    for (int p = 0; p < 2; p++) {
        int br = wn * 32 + p * 16 + bRowL;
        bRowOff[p] = br * 128;
        bXor[p] = (br & 7) << 4;
    }

    float acc[4][4][4] = {};

    loadChunk(0, 0);
    loadChunk(1, 1);

    for (int c = 0; c < 8; c++) {
        if (c < 6) cp_wait<1>(); else cp_wait<0>();
        __syncthreads();
        if (c + 2 < 8) loadChunk(c + 2, (c + 2) % NSTAGE);

        const uint32_t stage = sb + (c % NSTAGE) * STAGE_BYTES;
        const uint32_t aHi = stage, aLo = stage + 16384;
        const uint32_t bHi = stage + 32768, bLo = stage + 49152;

        #pragma unroll
        for (int s = 0; s < 4; s++) {          // k16 steps within 64-chunk
            uint32_t ah[4][4], al[4][4], bh[2][4], bl[2][4];
            uint32_t aCol = (uint32_t)(s * 32 + aKb * 16);
            uint32_t bCol = (uint32_t)(s * 32 + bKb * 16);
            #pragma unroll
            for (int i = 0; i < 4; i++) {
                ldm_x4(ah[i], aHi + aRowOff[i] + (aCol ^ aXor[i]));
                ldm_x4(al[i], aLo + aRowOff[i] + (aCol ^ aXor[i]));
            }
            #pragma unroll
            for (int p = 0; p < 2; p++) {
                ldm_x4(bh[p], bHi + bRowOff[p] + (bCol ^ bXor[p]));
                ldm_x4(bl[p], bLo + bRowOff[p] + (bCol ^ bXor[p]));
            }
            #pragma unroll
            for (int i = 0; i < 4; i++)
                #pragma unroll
                for (int j = 0; j < 4; j++) {
                    const uint32_t* bhf = &bh[j >> 1][(j & 1) * 2];
                    const uint32_t* blf = &bl[j >> 1][(j & 1) * 2];
                    mma16816(acc[i][j], ah[i], bhf);
                    mma16816(acc[i][j], ah[i], blf);
                    mma16816(acc[i][j], al[i], bhf);
                }
        }
        __syncthreads();
    }

    // ---- epilogue ----
    const int rlane = lane >> 2;
    const int clane = (lane & 3) * 2;
    #pragma unroll
    for (int i = 0; i < 4; i++) {
        int row0 = rowBase + wm * 64 + i * 16 + rlane;
        #pragma unroll
        for (int j = 0; j < 4; j++) {
            int col = colBase + wn * 32 + j * 8 + clane;
            float b0 = bias[col], b1v = bias[col + 1];
            float s0 = 1.f, s1 = 1.f, o0 = 0.f, o1 = 0.f;
            if (WHICH == 0) {
                s0 = rsqrtf(var[col] + BN_EPS) * gamma[col];
                s1 = rsqrtf(var[col + 1] + BN_EPS) * gamma[col + 1];
                o0 = beta[col] - mean[col] * s0;
                o1 = beta[col + 1] - mean[col + 1] * s1;
            }
            #pragma unroll
            for (int h = 0; h < 2; h++) {
                int row = row0 + h * 8;
                float v0 = acc[i][j][h * 2 + 0] + b0;
                float v1 = acc[i][j][h * 2 + 1] + b1v;
                if (WHICH == 0) { v0 = v0 * s0 + o0; v1 = v1 * s1 + o1; }
                v0 = v0 > 0.f ? v0 : expm1f(v0);
                v1 = v1 > 0.f ? v1 : expm1f(v1);
                if (WHICH == 0) {
                    __nv_bfloat16 h0 = __float2bfloat16_rn(v0);
                    __nv_bfloat16 h1 = __float2bfloat16_rn(v1);
                    *(__nv_bfloat162*)(g_Bh + (size_t)row * HD + col) = __nv_bfloat162(h0, h1);
                    __nv_bfloat16 l0 = __float2bfloat16_rn(v0 - __bfloat162float(h0));
                    __nv_bfloat16 l1 = __float2bfloat16_rn(v1 - __bfloat162float(h1));
                    *(__nv_bfloat162*)(g_Bl + (size_t)row * HD + col) = __nv_bfloat162(l0, l1);
                } else {
                    *(float2*)(g_z2 + (size_t)row * HD + col) = make_float2(v0, v1);
                }
            }
        }
    }
}

// ---------------- pool: s = softmax(z2 @ pool_w + pool_b) ----------------
__global__ __launch_bounds__(256) void pool_kernel(const float* __restrict__ pw,
                                                   const float* __restrict__ pb) {
    __shared__ float pws[CC * 513];
    __shared__ float pbs[CC];
    int tid = threadIdx.x;
    for (int i = tid; i < HD * CC; i += 256) {
        int k = i >> 4, c = i & 15;
        pws[c * 513 + k] = pw[i];
    }
    if (tid < CC) pbs[tid] = pb[tid];
    __syncthreads();
    int warp = tid >> 5, lane = tid & 31;
    int n = blockIdx.x * 8 + warp;
    const float* z = g_z2 + (size_t)n * HD;
    float acc[CC] = {};
    #pragma unroll
    for (int j = 0; j < 16; j++) {
        int k = lane + 32 * j;
        float zv = z[k];
        #pragma unroll
        for (int c = 0; c < CC; c++) acc[c] += zv * pws[c * 513 + k];
    }
    #pragma unroll
    for (int c = 0; c < CC; c++) acc[c] = warpSum(acc[c]);
    float mx = -INFINITY;
    #pragma unroll
    for (int c = 0; c < CC; c++) { acc[c] += pbs[c]; mx = fmaxf(mx, acc[c]); }
    float sum = 0.f;
    #pragma unroll
    for (int c = 0; c < CC; c++) { acc[c] = expf(acc[c] - mx); sum += acc[c]; }
    float inv = 1.f / sum;
    if (lane < CC) g_s[n * CC + lane] = acc[lane] * inv;
}

// ---------------- per-batch losses ----------------
__global__ __launch_bounds__(256) void loss_kernel(const int* __restrict__ ei,
                                                   float* __restrict__ out) {
    __shared__ float ssh[NN * CC];
    __shared__ float dsh[NN];
    __shared__ float wsh[CC], csh[CC];
    __shared__ float sAcc[4];
    int b = blockIdx.x, t = threadIdx.x;
    int lane = t & 31;

    for (int i = t; i < NN * CC; i += 256) ssh[i] = g_s[b * NN * CC + i];
    for (int i = t; i < NN; i += 256) dsh[i] = (float)g_deg[b * NN + i];
    if (t < CC) { wsh[t] = 0.f; csh[t] = 0.f; }
    if (t < 4) sAcc[t] = 0.f;
    __syncthreads();

    float wp[CC] = {}, cp[CC] = {};
    float td = 0.f;
    for (int n = t; n < NN; n += 256) {
        float d = dsh[n];
        td += d;
        #pragma unroll
        for (int c = 0; c < CC; c++) {
            float sv = ssh[n * CC + c];
            wp[c] += sv * d;
            cp[c] += sv;
        }
    }
    td = warpSum(td);
    #pragma unroll
    for (int c = 0; c < CC; c++) { wp[c] = warpSum(wp[c]); cp[c] = warpSum(cp[c]); }
    if (lane == 0) {
        atomicAdd(&sAcc[0], td);
        #pragma unroll
        for (int c = 0; c < CC; c++) { atomicAdd(&wsh[c], wp[c]); atomicAdd(&csh[c], cp[c]); }
    }

    int cc = t >> 4, kk = t & 15;
    float ssv = 0.f;
    for (int n = 0; n < NN; n++) ssv += ssh[n * CC + cc] * ssh[n * CC + kk];
    float s2 = warpSum(ssv * ssv);
    if (lane == 0) atomicAdd(&sAcc[2], s2);

    const int* srcp = ei;
    const int* dstp = ei + ETOT;
    float et = 0.f;
    for (int e = b * EB + t; e < (b + 1) * EB; e += 256) {
        int sl = srcp[e] - b * NN;
        int dl = dstp[e] - b * NN;
        float d2 = 0.f;
        #pragma unroll
        for (int c = 0; c < CC; c++) d2 += ssh[sl * CC + c] * ssh[dl * CC + c];
        et += d2;
    }
    et = warpSum(et);
    if (lane == 0) atomicAdd(&sAcc[1], et);
    __syncthreads();

    float fro = sqrtf(sAcc[2]);
    float dd = ssv / fro - ((cc == kk) ? 0.25f : 0.f);
    float dsq = warpSum(dd * dd);
    if (lane == 0) atomicAdd(&sAcc[3], dsq);
    __syncthreads();

    if (t == 0) {
        float m = sAcc[0] * 0.5f;
        float wsq = 0.f, cs2 = 0.f;
        #pragma unroll
        for (int c = 0; c < CC; c++) { wsq += wsh[c] * wsh[c]; cs2 += csh[c] * csh[c]; }
        float trace = sAcc[1] - wsq / (2.f * m);
        float spec = -trace / (2.f * m);
        float ortho = sqrtf(sAcc[3]);
        float cluster = sqrtf(cs2) / (float)NN * 4.f - 1.f;
        atomicAdd(out, (spec + ortho + cluster) * (1.f / (float)BB));
    }
}

// ---------------- launch ----------------
extern "C" void kernel_launch(void* const* d_in, const int* in_sizes, int n_in,
                              void* d_out, int out_size) {
    const int*   x      = (const int*)d_in[0];
    const int*   ei     = (const int*)d_in[1];
    const float* emb    = (const float*)d_in[3];
    const float* w1     = (const float*)d_in[4];
    const float* b1     = (const float*)d_in[5];
    const float* bn_g   = (const float*)d_in[6];
    const float* bn_b   = (const float*)d_in[7];
    const float* bn_m   = (const float*)d_in[8];
    const float* bn_v   = (const float*)d_in[9];
    const float* w2     = (const float*)d_in[10];
    const float* b2     = (const float*)d_in[11];
    const float* pool_w = (const float*)d_in[12];
    const float* pool_b = (const float*)d_in[13];
    float* out = (float*)d_out;

    cudaFuncSetAttribute(gemm_mma<0>, cudaFuncAttributeMaxDynamicSharedMemorySize, SMEM_GEMM);
    cudaFuncSetAttribute(gemm_mma<1>, cudaFuncAttributeMaxDynamicSharedMemorySize, SMEM_GEMM);

    init_kernel<<<(MROWS + 255) / 256, 256>>>(out);
    count_kernel<<<ETOT / 256, 256>>>(ei);
    scan_kernel<<<1, 1024>>>();
    fill_kernel<<<ETOT / 256, 256>>>(ei);
    wprep_kernel<<<HD * HD / 256, 256>>>(w1, w2);
    z0_kernel<<<MROWS, 128>>>(x, emb);

    dim3 gGrid(HD / 128, MROWS / 128);   // (4, 256)
    gemm_mma<0><<<gGrid, 256, SMEM_GEMM>>>(b1, bn_g, bn_b, bn_m, bn_v);
    gemm_mma<1><<<gGrid, 256, SMEM_GEMM>>>(b2, nullptr, nullptr, nullptr, nullptr);

    pool_kernel<<<MROWS / 8, 256>>>(pool_w, pool_b);
    loss_kernel<<<BB, 256>>>(ei, out);
}

// round 5
// speedup vs baseline: 2.3097x; 1.2349x over previous
#include <cuda_runtime.h>
#include <cuda_fp16.h>
#include <math.h>
#include <stdint.h>

// Problem constants
#define BB    64
#define NN    512
#define MROWS (BB*NN)        // 32768 nodes
#define DEG   8
#define ETOT  (MROWS*DEG)    // 262144 edges
#define EB    (NN*DEG)       // 4096 edges per batch
#define HD    512            // D == H == 512
#define CC    16
#define BN_EPS 1e-5f

// ---------------- static scratch ----------------
__device__ __align__(1024) __half g_A16[MROWS*HD];          // z0 fp16
__device__ __align__(1024) __half g_B16[MROWS*HD];          // z1 fp16
__device__ __align__(1024) __half g_W1h[HD*HD], g_W1l[HD*HD];  // [n][k] fp16 split
__device__ __align__(1024) __half g_W2h[HD*HD], g_W2l[HD*HD];
__device__ __align__(1024) float  g_logits[MROWS*CC];       // pre-softmax pool logits
__device__ float g_s[MROWS*CC];
__device__ int   g_deg[MROWS];
__device__ int   g_counts[MROWS];
__device__ int   g_cursor[MROWS];
__device__ int   g_off[MROWS+1];
__device__ int   g_csr[ETOT];

__device__ __forceinline__ float warpSum(float v) {
    #pragma unroll
    for (int o = 16; o; o >>= 1) v += __shfl_xor_sync(0xffffffffu, v, o);
    return v;
}

// ---------------- PTX helpers (sm_80+ portable) ----------------
__device__ __forceinline__ uint32_t smem_u32(const void* p) {
    uint32_t a;
    asm("{ .reg .u64 t; cvta.to.shared.u64 t, %1; cvt.u32.u64 %0, t; }" : "=r"(a) : "l"(p));
    return a;
}
__device__ __forceinline__ void cp16(uint32_t dst, const void* src) {
    asm volatile("cp.async.cg.shared.global [%0], [%1], 16;\n" :: "r"(dst), "l"(src));
}
__device__ __forceinline__ void cp_commit() {
    asm volatile("cp.async.commit_group;\n" ::: "memory");
}
template<int N>
__device__ __forceinline__ void cp_wait() {
    asm volatile("cp.async.wait_group %0;\n" :: "n"(N) : "memory");
}
__device__ __forceinline__ void ldm_x4(uint32_t* r, uint32_t addr) {
    asm volatile("ldmatrix.sync.aligned.m8n8.x4.shared.b16 {%0,%1,%2,%3}, [%4];"
                 : "=r"(r[0]), "=r"(r[1]), "=r"(r[2]), "=r"(r[3]) : "r"(addr));
}
__device__ __forceinline__ void mma16816(float* d, const uint32_t* a, const uint32_t* b) {
    asm volatile("mma.sync.aligned.m16n8k16.row.col.f32.f16.f16.f32 "
                 "{%0,%1,%2,%3}, {%4,%5,%6,%7}, {%8,%9}, {%0,%1,%2,%3};"
                 : "+f"(d[0]), "+f"(d[1]), "+f"(d[2]), "+f"(d[3])
                 : "r"(a[0]), "r"(a[1]), "r"(a[2]), "r"(a[3]), "r"(b[0]), "r"(b[1]));
}

// ---------------- init: zero counters, logits, output ----------------
__global__ void init_kernel(float* out) {
    int i = blockIdx.x * blockDim.x + threadIdx.x;
    if (i < MROWS) {
        g_counts[i] = 0; g_cursor[i] = 0; g_deg[i] = 0;
        float4 z = make_float4(0.f, 0.f, 0.f, 0.f);
        float4* lg = (float4*)(g_logits + i * CC);
        lg[0] = z; lg[1] = z; lg[2] = z; lg[3] = z;
    }
    if (i == 0) out[0] = 0.f;
}

// ---------------- CSR build ----------------
__global__ void count_kernel(const int* __restrict__ ei) {
    int e = blockIdx.x * blockDim.x + threadIdx.x;
    if (e < ETOT) {
        atomicAdd(&g_counts[ei[ETOT + e]], 1);
        atomicAdd(&g_deg[ei[e]], 1);
    }
}

__global__ void scan_kernel() {
    __shared__ int part[1024];
    int t = threadIdx.x;
    int base = t * 32;
    int local[32];
    int s = 0;
    #pragma unroll
    for (int i = 0; i < 32; i++) { local[i] = s; s += g_counts[base + i]; }
    part[t] = s;
    __syncthreads();
    for (int off = 1; off < 1024; off <<= 1) {
        int v = (t >= off) ? part[t - off] : 0;
        __syncthreads();
        part[t] += v;
        __syncthreads();
    }
    int pre = (t == 0) ? 0 : part[t - 1];
    #pragma unroll
    for (int i = 0; i < 32; i++) g_off[base + i] = pre + local[i];
    if (t == 1023) g_off[MROWS] = part[1023];
}

__global__ void fill_kernel(const int* __restrict__ ei) {
    int e = blockIdx.x * blockDim.x + threadIdx.x;
    if (e < ETOT) {
        int d = ei[ETOT + e];
        int p = atomicAdd(&g_cursor[d], 1);
        g_csr[g_off[d] + p] = ei[e];
    }
}

// ---------------- weight prep: transpose + fp16 split ----------------
__global__ void wprep_kernel(const float* __restrict__ w1, const float* __restrict__ w2) {
    int i = blockIdx.x * blockDim.x + threadIdx.x;  // i = k*512 + n
    int k = i >> 9, n = i & 511;
    float v1 = w1[i];
    __half h1 = __float2half_rn(v1);
    g_W1h[n * HD + k] = h1;
    g_W1l[n * HD + k] = __float2half_rn(v1 - __half2float(h1));
    float v2 = w2[i];
    __half h2 = __float2half_rn(v2);
    g_W2h[n * HD + k] = h2;
    g_W2l[n * HD + k] = __float2half_rn(v2 - __half2float(h2));
}

// ---------------- z0 = emb[x] + segment_sum(emb[x[src]], dst), fp16 ----------------
__global__ void z0_kernel(const int* __restrict__ x, const float* __restrict__ emb) {
    int n = blockIdx.x;
    int t = threadIdx.x;  // 128 threads x float4
    const float4* emb4 = (const float4*)emb;
    float4 acc = emb4[x[n] * 128 + t];
    int e1 = g_off[n + 1];
    for (int e = g_off[n]; e < e1; e++) {
        int sx = x[g_csr[e]];
        float4 v = emb4[sx * 128 + t];
        acc.x += v.x; acc.y += v.y; acc.z += v.z; acc.w += v.w;
    }
    int base = n * HD + t * 4;
    *(__half2*)(g_A16 + base)     = __floats2half2_rn(acc.x, acc.y);
    *(__half2*)(g_A16 + base + 2) = __floats2half2_rn(acc.z, acc.w);
}

// ---------------- mma.sync 2-term fp16-split GEMM ----------------
// 128x128 CTA tile, 8 warps (2x4), K-chunk 64, 4-stage cp.async pipeline.
// D = A * Wh + A * Wl  (A single fp16, W split fp16 hi/lo)
// WHICH==0: z1 = elu(bn(z0 @ w1 + b1)) -> g_B16 (fp16)
// WHICH==1: z2 = elu(z1 @ w2 + b2), fused pool: atomicAdd partial z2@pool_w logits

#define STAGE_BYTES 49152          // A 16K | Wh 16K | Wl 16K
#define NSTAGE 4
#define SMEM_GEMM (NSTAGE * STAGE_BYTES)   // 192 KB

template<int WHICH>
__global__ __launch_bounds__(256, 1) void gemm_mma(
    const float* __restrict__ bias, const float* __restrict__ gamma,
    const float* __restrict__ beta, const float* __restrict__ mean,
    const float* __restrict__ var, const float* __restrict__ poolw)
{
    extern __shared__ __align__(1024) char smem[];
    const uint32_t sb = smem_u32(smem);
    const int tid = threadIdx.x;
    const int wid = tid >> 5, lane = tid & 31;
    const int wm = wid & 1;        // 0..1 -> 64 rows
    const int wn = wid >> 1;       // 0..3 -> 32 cols
    const int rowBase = blockIdx.y * 128;
    const int colBase = blockIdx.x * 128;

    const __half* __restrict__ Ap  = WHICH ? g_B16 : g_A16;
    const __half* __restrict__ Whp = WHICH ? g_W2h : g_W1h;
    const __half* __restrict__ Wlp = WHICH ? g_W2l : g_W1l;

    // ---- loader: 12 x 16B cp.async per thread per chunk ----
    auto loadChunk = [&](int c, int s) {
        const uint32_t stage = sb + s * STAGE_BYTES;
        #pragma unroll
        for (int it = 0; it < 12; it++) {
            int idx = tid + it * 256;
            int q = idx >> 10;                    // 0=A, 1=Wh, 2=Wl
            int r = (idx & 1023) >> 3;
            int cc = idx & 7;
            const __half* base = (q == 0) ? Ap : (q == 1) ? Whp : Wlp;
            int grow = ((q == 0) ? rowBase : colBase) + r;
            const __half* src = base + (size_t)grow * HD + c * 64 + cc * 8;
            uint32_t off = r * 128 + cc * 16;
            uint32_t sw = off ^ ((off >> 3) & 0x70);
            cp16(stage + q * 16384 + sw, src);
        }
        cp_commit();
    };

    // ---- ldmatrix per-thread addressing ----
    const int g = lane >> 3;                  // 0..3
    const int aRowL = (g & 1) * 8 + (lane & 7);
    const int aKb   = (g >> 1);
    const int bRowL = (g >> 1) * 8 + (lane & 7);
    const int bKb   = (g & 1);

    uint32_t aRowOff[4], aXor[4];
    #pragma unroll
    for (int i = 0; i < 4; i++) {
        int ar = wm * 64 + i * 16 + aRowL;
        aRowOff[i] = ar * 128;
        aXor[i] = (ar & 7) << 4;
    }
    uint32_t bRowOff[2], bXor[2];
    #pragma unroll
    for (int p = 0; p < 2; p++) {
        int br = wn * 32 + p * 16 + bRowL;
        bRowOff[p] = br * 128;
        bXor[p] = (br & 7) << 4;
    }

    float acc[4][4][4] = {};

    loadChunk(0, 0);
    loadChunk(1, 1);
    loadChunk(2, 2);

    for (int c = 0; c < 8; c++) {
        if (c <= 5) cp_wait<2>(); else if (c == 6) cp_wait<1>(); else cp_wait<0>();
        __syncthreads();
        if (c + 3 < 8) loadChunk(c + 3, (c + 3) & 3);

        const uint32_t stage = sb + (c & 3) * STAGE_BYTES;
        const uint32_t aPl = stage, bHi = stage + 16384, bLo = stage + 32768;

        #pragma unroll
        for (int s = 0; s < 4; s++) {          // k16 steps within 64-chunk
            uint32_t ah[4][4], bh[2][4], bl[2][4];
            uint32_t aCol = (uint32_t)(s * 32 + aKb * 16);
            uint32_t bCol = (uint32_t)(s * 32 + bKb * 16);
            #pragma unroll
            for (int i = 0; i < 4; i++)
                ldm_x4(ah[i], aPl + aRowOff[i] + (aCol ^ aXor[i]));
            #pragma unroll
            for (int p = 0; p < 2; p++) {
                ldm_x4(bh[p], bHi + bRowOff[p] + (bCol ^ bXor[p]));
                ldm_x4(bl[p], bLo + bRowOff[p] + (bCol ^ bXor[p]));
            }
            #pragma unroll
            for (int i = 0; i < 4; i++)
                #pragma unroll
                for (int j = 0; j < 4; j++) {
                    const uint32_t* bhf = &bh[j >> 1][(j & 1) * 2];
                    const uint32_t* blf = &bl[j >> 1][(j & 1) * 2];
                    mma16816(acc[i][j], ah[i], bhf);
                    mma16816(acc[i][j], ah[i], blf);
                }
        }
        __syncthreads();
    }

    // ---- epilogue ----
    const int rlane = lane >> 2;
    const int clane = (lane & 3) * 2;
    float* sE = (float*)smem;                 // [128][129] for WHICH==1

    #pragma unroll
    for (int i = 0; i < 4; i++) {
        int rl0 = wm * 64 + i * 16 + rlane;
        #pragma unroll
        for (int j = 0; j < 4; j++) {
            int cl = wn * 32 + j * 8 + clane;
            int col = colBase + cl;
            float b0 = bias[col], b1v = bias[col + 1];
            float s0 = 1.f, s1 = 1.f, o0 = 0.f, o1 = 0.f;
            if (WHICH == 0) {
                s0 = rsqrtf(var[col] + BN_EPS) * gamma[col];
                s1 = rsqrtf(var[col + 1] + BN_EPS) * gamma[col + 1];
                o0 = beta[col] - mean[col] * s0;
                o1 = beta[col + 1] - mean[col + 1] * s1;
            }
            #pragma unroll
            for (int h = 0; h < 2; h++) {
                int rl = rl0 + h * 8;
                float v0 = acc[i][j][h * 2 + 0] + b0;
                float v1 = acc[i][j][h * 2 + 1] + b1v;
                if (WHICH == 0) { v0 = v0 * s0 + o0; v1 = v1 * s1 + o1; }
                v0 = v0 > 0.f ? v0 : expm1f(v0);
                v1 = v1 > 0.f ? v1 : expm1f(v1);
                if (WHICH == 0) {
                    *(__half2*)(g_B16 + (size_t)(rowBase + rl) * HD + col) =
                        __floats2half2_rn(v0, v1);
                } else {
                    sE[rl * 129 + cl] = v0;
                    sE[rl * 129 + cl + 1] = v1;
                }
            }
        }
    }

    if (WHICH == 1) {
        // fused pool: partial logits = sE(128x128) @ pool_w[colBase:colBase+128, 0:16]
        float* sPw = sE + 128 * 129;          // [128][16]
        __syncthreads();
        #pragma unroll
        for (int jj = 0; jj < 8; jj++) {
            int idx = tid * 8 + jj;
            int k = idx >> 4, cch = idx & 15;
            sPw[k * 16 + cch] = poolw[(size_t)(colBase + k) * CC + cch];
        }
        __syncthreads();
        int r = tid & 127;
        int c0 = (tid >> 7) * 8;
        float a8[8] = {};
        #pragma unroll 4
        for (int k = 0; k < 128; k++) {
            float zv = sE[r * 129 + k];
            #pragma unroll
            for (int c8 = 0; c8 < 8; c8++) a8[c8] += zv * sPw[k * 16 + c0 + c8];
        }
        float* dst = g_logits + (size_t)(rowBase + r) * CC + c0;
        #pragma unroll
        for (int c8 = 0; c8 < 8; c8++) atomicAdd(dst + c8, a8[c8]);
    }
}

// ---------------- softmax: s = softmax(logits + pool_b) ----------------
__global__ __launch_bounds__(256) void softmax_kernel(const float* __restrict__ pb) {
    int n = blockIdx.x * blockDim.x + threadIdx.x;
    float l[CC];
    const float4* src = (const float4*)(g_logits + (size_t)n * CC);
    #pragma unroll
    for (int q = 0; q < 4; q++) ((float4*)l)[q] = src[q];
    float mx = -INFINITY;
    #pragma unroll
    for (int c = 0; c < CC; c++) { l[c] += pb[c]; mx = fmaxf(mx, l[c]); }
    float sum = 0.f;
    #pragma unroll
    for (int c = 0; c < CC; c++) { l[c] = expf(l[c] - mx); sum += l[c]; }
    float inv = 1.f / sum;
    float4* dst = (float4*)(g_s + (size_t)n * CC);
    #pragma unroll
    for (int c = 0; c < CC; c++) l[c] *= inv;
    #pragma unroll
    for (int q = 0; q < 4; q++) dst[q] = ((float4*)l)[q];
}

// ---------------- per-batch losses ----------------
__global__ __launch_bounds__(256) void loss_kernel(const int* __restrict__ ei,
                                                   float* __restrict__ out) {
    __shared__ float ssh[NN * CC];
    __shared__ float dsh[NN];
    __shared__ float wsh[CC], csh[CC];
    __shared__ float sAcc[4];
    int b = blockIdx.x, t = threadIdx.x;
    int lane = t & 31;

    for (int i = t; i < NN * CC; i += 256) ssh[i] = g_s[b * NN * CC + i];
    for (int i = t; i < NN; i += 256) dsh[i] = (float)g_deg[b * NN + i];
    if (t < CC) { wsh[t] = 0.f; csh[t] = 0.f; }
    if (t < 4) sAcc[t] = 0.f;
    __syncthreads();

    float wp[CC] = {}, cp[CC] = {};
    float td = 0.f;
    for (int n = t; n < NN; n += 256) {
        float d = dsh[n];
        td += d;
        #pragma unroll
        for (int c = 0; c < CC; c++) {
            float sv = ssh[n * CC + c];
            wp[c] += sv * d;
            cp[c] += sv;
        }
    }
    td = warpSum(td);
    #pragma unroll
    for (int c = 0; c < CC; c++) { wp[c] = warpSum(wp[c]); cp[c] = warpSum(cp[c]); }
    if (lane == 0) {
        atomicAdd(&sAcc[0], td);
        #pragma unroll
        for (int c = 0; c < CC; c++) { atomicAdd(&wsh[c], wp[c]); atomicAdd(&csh[c], cp[c]); }
    }

    int cc = t >> 4, kk = t & 15;
    float ssv = 0.f;
    for (int n = 0; n < NN; n++) ssv += ssh[n * CC + cc] * ssh[n * CC + kk];
    float s2 = warpSum(ssv * ssv);
    if (lane == 0) atomicAdd(&sAcc[2], s2);

    const int* srcp = ei;
    const int* dstp = ei + ETOT;
    float et = 0.f;
    for (int e = b * EB + t; e < (b + 1) * EB; e += 256) {
        int sl = srcp[e] - b * NN;
        int dl = dstp[e] - b * NN;
        float d2 = 0.f;
        #pragma unroll
        for (int c = 0; c < CC; c++) d2 += ssh[sl * CC + c] * ssh[dl * CC + c];
        et += d2;
    }
    et = warpSum(et);
    if (lane == 0) atomicAdd(&sAcc[1], et);
    __syncthreads();

    float fro = sqrtf(sAcc[2]);
    float dd = ssv / fro - ((cc == kk) ? 0.25f : 0.f);
    float dsq = warpSum(dd * dd);
    if (lane == 0) atomicAdd(&sAcc[3], dsq);
    __syncthreads();

    if (t == 0) {
        float m = sAcc[0] * 0.5f;
        float wsq = 0.f, cs2 = 0.f;
        #pragma unroll
        for (int c = 0; c < CC; c++) { wsq += wsh[c] * wsh[c]; cs2 += csh[c] * csh[c]; }
        float trace = sAcc[1] - wsq / (2.f * m);
        float spec = -trace / (2.f * m);
        float ortho = sqrtf(sAcc[3]);
        float cluster = sqrtf(cs2) / (float)NN * 4.f - 1.f;
        atomicAdd(out, (spec + ortho + cluster) * (1.f / (float)BB));
    }
}

// ---------------- launch ----------------
extern "C" void kernel_launch(void* const* d_in, const int* in_sizes, int n_in,
                              void* d_out, int out_size) {
    const int*   x      = (const int*)d_in[0];
    const int*   ei     = (const int*)d_in[1];
    const float* emb    = (const float*)d_in[3];
    const float* w1     = (const float*)d_in[4];
    const float* b1     = (const float*)d_in[5];
    const float* bn_g   = (const float*)d_in[6];
    const float* bn_b   = (const float*)d_in[7];
    const float* bn_m   = (const float*)d_in[8];
    const float* bn_v   = (const float*)d_in[9];
    const float* w2     = (const float*)d_in[10];
    const float* b2     = (const float*)d_in[11];
    const float* pool_w = (const float*)d_in[12];
    const float* pool_b = (const float*)d_in[13];
    float* out = (float*)d_out;

    cudaFuncSetAttribute(gemm_mma<0>, cudaFuncAttributeMaxDynamicSharedMemorySize, SMEM_GEMM);
    cudaFuncSetAttribute(gemm_mma<1>, cudaFuncAttributeMaxDynamicSharedMemorySize, SMEM_GEMM);

    init_kernel<<<(MROWS + 255) / 256, 256>>>(out);
    count_kernel<<<ETOT / 256, 256>>>(ei);
    scan_kernel<<<1, 1024>>>();
    fill_kernel<<<ETOT / 256, 256>>>(ei);
    wprep_kernel<<<HD * HD / 256, 256>>>(w1, w2);
    z0_kernel<<<MROWS, 128>>>(x, emb);

    dim3 gGrid(HD / 128, MROWS / 128);   // (4, 256)
    gemm_mma<0><<<gGrid, 256, SMEM_GEMM>>>(b1, bn_g, bn_b, bn_m, bn_v, nullptr);
    gemm_mma<1><<<gGrid, 256, SMEM_GEMM>>>(b2, nullptr, nullptr, nullptr, nullptr, pool_w);

    softmax_kernel<<<MROWS / 256, 256>>>(pool_b);
    loss_kernel<<<BB, 256>>>(ei, out);
}

// round 7
// speedup vs baseline: 3.2814x; 1.4207x over previous
#include <cuda_runtime.h>
#include <cuda_fp16.h>
#include <math.h>
#include <stdint.h>

// Problem constants
#define BB    64
#define NN    512
#define MROWS (BB*NN)        // 32768 nodes
#define DEG   8
#define ETOT  (MROWS*DEG)    // 262144 edges
#define EB    (NN*DEG)       // 4096 edges per batch
#define HD    512            // D == H == 512
#define CC    16
#define VOCAB 10000
#define BN_EPS 1e-5f

// ---------------- static scratch ----------------
__device__ __align__(1024) __half g_E16[VOCAB*HD];          // emb fp16
__device__ __align__(1024) __half g_A16[MROWS*HD];          // z0 fp16
__device__ __align__(1024) __half g_B16[MROWS*HD];          // z1 fp16
__device__ __align__(1024) __half g_W1[HD*HD];              // [n][k] fp16
__device__ __align__(1024) __half g_W2[HD*HD];
__device__ __align__(1024) float  g_logits[MROWS*CC];       // pre-softmax pool logits
__device__ float g_s[MROWS*CC];
__device__ int   g_deg[MROWS];
__device__ int   g_counts[MROWS];
__device__ int   g_cursor[MROWS];
__device__ int   g_off[MROWS+1];
__device__ int   g_csr[ETOT];

__device__ __forceinline__ float warpSum(float v) {
    #pragma unroll
    for (int o = 16; o; o >>= 1) v += __shfl_xor_sync(0xffffffffu, v, o);
    return v;
}

// ---------------- PTX helpers (sm_80+ portable) ----------------
__device__ __forceinline__ uint32_t smem_u32(const void* p) {
    uint32_t a;
    asm("{ .reg .u64 t; cvta.to.shared.u64 t, %1; cvt.u32.u64 %0, t; }" : "=r"(a) : "l"(p));
    return a;
}
__device__ __forceinline__ void cp16(uint32_t dst, const void* src) {
    asm volatile("cp.async.cg.shared.global [%0], [%1], 16;\n" :: "r"(dst), "l"(src));
}
__device__ __forceinline__ void cp_commit() {
    asm volatile("cp.async.commit_group;\n" ::: "memory");
}
template<int N>
__device__ __forceinline__ void cp_wait() {
    asm volatile("cp.async.wait_group %0;\n" :: "n"(N) : "memory");
}
__device__ __forceinline__ void ldm_x4(uint32_t* r, uint32_t addr) {
    asm volatile("ldmatrix.sync.aligned.m8n8.x4.shared.b16 {%0,%1,%2,%3}, [%4];"
                 : "=r"(r[0]), "=r"(r[1]), "=r"(r[2]), "=r"(r[3]) : "r"(addr));
}
__device__ __forceinline__ void mma16816(float* d, const uint32_t* a, const uint32_t* b) {
    asm volatile("mma.sync.aligned.m16n8k16.row.col.f32.f16.f16.f32 "
                 "{%0,%1,%2,%3}, {%4,%5,%6,%7}, {%8,%9}, {%0,%1,%2,%3};"
                 : "+f"(d[0]), "+f"(d[1]), "+f"(d[2]), "+f"(d[3])
                 : "r"(a[0]), "r"(a[1]), "r"(a[2]), "r"(a[3]), "r"(b[0]), "r"(b[1]));
}

// ---------------- init: zero counters, logits, output ----------------
__global__ void init_kernel(float* out) {
    int i = blockIdx.x * blockDim.x + threadIdx.x;
    if (i < MROWS) {
        g_counts[i] = 0; g_cursor[i] = 0; g_deg[i] = 0;
        float4 z = make_float4(0.f, 0.f, 0.f, 0.f);
        float4* lg = (float4*)(g_logits + i * CC);
        lg[0] = z; lg[1] = z; lg[2] = z; lg[3] = z;
    }
    if (i == 0) out[0] = 0.f;
}

// ---------------- emb -> fp16 ----------------
__global__ void econv_kernel(const float* __restrict__ emb) {
    int i = blockIdx.x * blockDim.x + threadIdx.x;   // element pairs
    float2 v = ((const float2*)emb)[i];
    ((__half2*)g_E16)[i] = __floats2half2_rn(v.x, v.y);
}

// ---------------- CSR build ----------------
__global__ void count_kernel(const int* __restrict__ ei) {
    int e = blockIdx.x * blockDim.x + threadIdx.x;
    if (e < ETOT) {
        atomicAdd(&g_counts[ei[ETOT + e]], 1);
        atomicAdd(&g_deg[ei[e]], 1);
    }
}

__global__ void scan_kernel() {
    __shared__ int part[1024];
    int t = threadIdx.x;
    int base = t * 32;
    int local[32];
    int s = 0;
    #pragma unroll
    for (int i = 0; i < 32; i++) { local[i] = s; s += g_counts[base + i]; }
    part[t] = s;
    __syncthreads();
    for (int off = 1; off < 1024; off <<= 1) {
        int v = (t >= off) ? part[t - off] : 0;
        __syncthreads();
        part[t] += v;
        __syncthreads();
    }
    int pre = (t == 0) ? 0 : part[t - 1];
    #pragma unroll
    for (int i = 0; i < 32; i++) g_off[base + i] = pre + local[i];
    if (t == 1023) g_off[MROWS] = part[1023];
}

__global__ void fill_kernel(const int* __restrict__ ei) {
    int e = blockIdx.x * blockDim.x + threadIdx.x;
    if (e < ETOT) {
        int d = ei[ETOT + e];
        int p = atomicAdd(&g_cursor[d], 1);
        g_csr[g_off[d] + p] = ei[e];
    }
}

// ---------------- weight prep: transpose + fp16 ----------------
__global__ void wprep_kernel(const float* __restrict__ w1, const float* __restrict__ w2) {
    int i = blockIdx.x * blockDim.x + threadIdx.x;  // i = k*512 + n
    int k = i >> 9, n = i & 511;
    g_W1[n * HD + k] = __float2half_rn(w1[i]);
    g_W2[n * HD + k] = __float2half_rn(w2[i]);
}

// ---------------- z0 = emb16[x] + segment_sum(emb16[x[src]], dst), fp16 out ----------------
__global__ void z0_kernel(const int* __restrict__ x) {
    int n = blockIdx.x;
    int t = threadIdx.x;  // 128 threads; 4 halves (8B) each
    const uint2* emb2 = (const uint2*)g_E16;   // 4 halves per uint2, 128 per row
    uint2 hv = emb2[(size_t)x[n] * 128 + t];
    __half2 p0 = *(__half2*)&hv.x, p1 = *(__half2*)&hv.y;
    float2 a0 = __half22float2(p0), a1 = __half22float2(p1);
    int e1 = g_off[n + 1];
    for (int e = g_off[n]; e < e1; e++) {
        int sx = x[g_csr[e]];
        uint2 v = emb2[(size_t)sx * 128 + t];
        float2 b0 = __half22float2(*(__half2*)&v.x);
        float2 b1 = __half22float2(*(__half2*)&v.y);
        a0.x += b0.x; a0.y += b0.y; a1.x += b1.x; a1.y += b1.y;
    }
    uint2 out;
    *(__half2*)&out.x = __floats2half2_rn(a0.x, a0.y);
    *(__half2*)&out.y = __floats2half2_rn(a1.x, a1.y);
    ((uint2*)g_A16)[(size_t)n * 128 + t] = out;
}

// ---------------- mma.sync fp16 GEMM ----------------
// 128x128 CTA tile, 8 warps (2x4), K-chunk 64, 3-stage cp.async pipeline, 2 CTAs/SM.
// WHICH==0: z1 = elu(bn(z0 @ w1 + b1)) -> g_B16 (fp16)
// WHICH==1: z2 = elu(z1 @ w2 + b2), fused pool: atomicAdd partial z2@pool_w logits

#define STAGE_BYTES 32768          // A 16K | W 16K
#define NSTAGE 3
#define SMEM_GEMM (NSTAGE * STAGE_BYTES)   // 96 KB

template<int WHICH>
__global__ __launch_bounds__(256, 2) void gemm_mma(
    const float* __restrict__ bias, const float* __restrict__ gamma,
    const float* __restrict__ beta, const float* __restrict__ mean,
    const float* __restrict__ var, const float* __restrict__ poolw)
{
    extern __shared__ __align__(1024) char smem[];
    const uint32_t sb = smem_u32(smem);
    const int tid = threadIdx.x;
    const int wid = tid >> 5, lane = tid & 31;
    const int wm = wid & 1;        // 0..1 -> 64 rows
    const int wn = wid >> 1;       // 0..3 -> 32 cols
    const int rowBase = blockIdx.y * 128;
    const int colBase = blockIdx.x * 128;

    const __half* __restrict__ Ap = WHICH ? g_B16 : g_A16;
    const __half* __restrict__ Wp = WHICH ? g_W2 : g_W1;

    // ---- loader: 8 x 16B cp.async per thread per chunk ----
    auto loadChunk = [&](int c, int s) {
        const uint32_t stage = sb + s * STAGE_BYTES;
        #pragma unroll
        for (int it = 0; it < 8; it++) {
            int idx = tid + it * 256;
            int q = idx >> 10;                    // 0=A, 1=W
            int r = (idx & 1023) >> 3;
            int cc = idx & 7;
            const __half* base = q ? Wp : Ap;
            int grow = (q ? colBase : rowBase) + r;
            const __half* src = base + (size_t)grow * HD + c * 64 + cc * 8;
            uint32_t off = r * 128 + cc * 16;
            uint32_t sw = off ^ ((off >> 3) & 0x70);
            cp16(stage + q * 16384 + sw, src);
        }
        cp_commit();
    };

    // ---- ldmatrix per-thread addressing ----
    const int g = lane >> 3;                  // 0..3
    const int aRowL = (g & 1) * 8 + (lane & 7);
    const int aKb   = (g >> 1);
    const int bRowL = (g >> 1) * 8 + (lane & 7);
    const int bKb   = (g & 1);

    uint32_t aRowOff[4], aXor[4];
    #pragma unroll
    for (int i = 0; i < 4; i++) {
        int ar = wm * 64 + i * 16 + aRowL;
        aRowOff[i] = ar * 128;
        aXor[i] = (ar & 7) << 4;
    }
    uint32_t bRowOff[2], bXor[2];
    #pragma unroll
    for (int p = 0; p < 2; p++) {
        int br = wn * 32 + p * 16 + bRowL;
        bRowOff[p] = br * 128;
        bXor[p] = (br & 7) << 4;
    }

    float acc[4][4][4] = {};

    loadChunk(0, 0);
    loadChunk(1, 1);

    for (int c = 0; c < 8; c++) {
        if (c < 7) cp_wait<1>(); else cp_wait<0>();
        __syncthreads();
        if (c + 2 < 8) loadChunk(c + 2, (c + 2) % NSTAGE);

        const uint32_t stage = sb + (c % NSTAGE) * STAGE_BYTES;
        const uint32_t aPl = stage, bPl = stage + 16384;

        #pragma unroll
        for (int s = 0; s < 4; s++) {          // k16 steps within 64-chunk
            uint32_t ah[4][4], bh[2][4];
            uint32_t aCol = (uint32_t)(s * 32 + aKb * 16);
            uint32_t bCol = (uint32_t)(s * 32 + bKb * 16);
            #pragma unroll
            for (int i = 0; i < 4; i++)
                ldm_x4(ah[i], aPl + aRowOff[i] + (aCol ^ aXor[i]));
            #pragma unroll
            for (int p = 0; p < 2; p++)
                ldm_x4(bh[p], bPl + bRowOff[p] + (bCol ^ bXor[p]));
            #pragma unroll
            for (int i = 0; i < 4; i++)
                #pragma unroll
                for (int j = 0; j < 4; j++)
                    mma16816(acc[i][j], ah[i], &bh[j >> 1][(j & 1) * 2]);
        }
        __syncthreads();
    }
    __syncthreads();   // final chunk's stage overlaps epilogue smem reuse

    // ---- epilogue ----
    const int rlane = lane >> 2;
    const int clane = (lane & 3) * 2;
    float* sE = (float*)smem;                 // [128][129] for WHICH==1

    #pragma unroll
    for (int i = 0; i < 4; i++) {
        int rl0 = wm * 64 + i * 16 + rlane;
        #pragma unroll
        for (int j = 0; j < 4; j++) {
            int cl = wn * 32 + j * 8 + clane;
            int col = colBase + cl;
            float b0 = bias[col], b1v = bias[col + 1];
            float s0 = 1.f, s1 = 1.f, o0 = 0.f, o1 = 0.f;
            if (WHICH == 0) {
                s0 = rsqrtf(var[col] + BN_EPS) * gamma[col];
                s1 = rsqrtf(var[col + 1] + BN_EPS) * gamma[col + 1];
                o0 = beta[col] - mean[col] * s0;
                o1 = beta[col + 1] - mean[col + 1] * s1;
            }
            #pragma unroll
            for (int h = 0; h < 2; h++) {
                int rl = rl0 + h * 8;
                float v0 = acc[i][j][h * 2 + 0] + b0;
                float v1 = acc[i][j][h * 2 + 1] + b1v;
                if (WHICH == 0) { v0 = v0 * s0 + o0; v1 = v1 * s1 + o1; }
                v0 = v0 > 0.f ? v0 : expm1f(v0);
                v1 = v1 > 0.f ? v1 : expm1f(v1);
                if (WHICH == 0) {
                    *(__half2*)(g_B16 + (size_t)(rowBase + rl) * HD + col) =
                        __floats2half2_rn(v0, v1);
                } else {
                    sE[rl * 129 + cl] = v0;
                    sE[rl * 129 + cl + 1] = v1;
                }
            }
        }
    }

    if (WHICH == 1) {
        // fused pool: partial logits = sE(128x128) @ pool_w[colBase:colBase+128, 0:16]
        float* sPw = sE + 128 * 129;          // [128][16] = 8 KB
        __syncthreads();
        #pragma unroll
        for (int jj = 0; jj < 8; jj++) {
            int idx = tid * 8 + jj;
            int k = idx >> 4, cch = idx & 15;
            sPw[k * 16 + cch] = poolw[(size_t)(colBase + k) * CC + cch];
        }
        __syncthreads();
        int r = tid & 127;
        int c0 = (tid >> 7) * 8;
        float a8[8] = {};
        #pragma unroll 4
        for (int k = 0; k < 128; k++) {
            float zv = sE[r * 129 + k];
            #pragma unroll
            for (int c8 = 0; c8 < 8; c8++) a8[c8] += zv * sPw[k * 16 + c0 + c8];
        }
        float* dst = g_logits + (size_t)(rowBase + r) * CC + c0;
        #pragma unroll
        for (int c8 = 0; c8 < 8; c8++) atomicAdd(dst + c8, a8[c8]);
    }
}

// ---------------- softmax: s = softmax(logits + pool_b) ----------------
__global__ __launch_bounds__(256) void softmax_kernel(const float* __restrict__ pb) {
    int n = blockIdx.x * blockDim.x + threadIdx.x;
    float l[CC];
    const float4* src = (const float4*)(g_logits + (size_t)n * CC);
    #pragma unroll
    for (int q = 0; q < 4; q++) ((float4*)l)[q] = src[q];
    float mx = -INFINITY;
    #pragma unroll
    for (int c = 0; c < CC; c++) { l[c] += pb[c]; mx = fmaxf(mx, l[c]); }
    float sum = 0.f;
    #pragma unroll
    for (int c = 0; c < CC; c++) { l[c] = expf(l[c] - mx); sum += l[c]; }
    float inv = 1.f / sum;
    float4* dst = (float4*)(g_s + (size_t)n * CC);
    #pragma unroll
    for (int c = 0; c < CC; c++) l[c] *= inv;
    #pragma unroll
    for (int q = 0; q < 4; q++) dst[q] = ((float4*)l)[q];
}

// ---------------- per-batch losses ----------------
__global__ __launch_bounds__(256) void loss_kernel(const int* __restrict__ ei,
                                                   float* __restrict__ out) {
    __shared__ float ssh[NN * CC];
    __shared__ float dsh[NN];
    __shared__ float wsh[CC], csh[CC];
    __shared__ float sAcc[4];
    int b = blockIdx.x, t = threadIdx.x;
    int lane = t & 31;

    for (int i = t; i < NN * CC; i += 256) ssh[i] = g_s[b * NN * CC + i];
    for (int i = t; i < NN; i += 256) dsh[i] = (float)g_deg[b * NN + i];
    if (t < CC) { wsh[t] = 0.f; csh[t] = 0.f; }
    if (t < 4) sAcc[t] = 0.f;
    __syncthreads();

    float wp[CC] = {}, cp[CC] = {};
    float td = 0.f;
    for (int n = t; n < NN; n += 256) {
        float d = dsh[n];
        td += d;
        #pragma unroll
        for (int c = 0; c < CC; c++) {
            float sv = ssh[n * CC + c];
            wp[c] += sv * d;
            cp[c] += sv;
        }
    }
    td = warpSum(td);
    #pragma unroll
    for (int c = 0; c < CC; c++) { wp[c] = warpSum(wp[c]); cp[c] = warpSum(cp[c]); }
    if (lane == 0) {
        atomicAdd(&sAcc[0], td);
        #pragma unroll
        for (int c = 0; c < CC; c++) { atomicAdd(&wsh[c], wp[c]); atomicAdd(&csh[c], cp[c]); }
    }

    int cc = t >> 4, kk = t & 15;
    float ssv = 0.f;
    for (int n = 0; n < NN; n++) ssv += ssh[n * CC + cc] * ssh[n * CC + kk];
    float s2 = warpSum(ssv * ssv);
    if (lane == 0) atomicAdd(&sAcc[2], s2);

    const int* srcp = ei;
    const int* dstp = ei + ETOT;
    float et = 0.f;
    for (int e = b * EB + t; e < (b + 1) * EB; e += 256) {
        int sl = srcp[e] - b * NN;
        int dl = dstp[e] - b * NN;
        float d2 = 0.f;
        #pragma unroll
        for (int c = 0; c < CC; c++) d2 += ssh[sl * CC + c] * ssh[dl * CC + c];
        et += d2;
    }
    et = warpSum(et);
    if (lane == 0) atomicAdd(&sAcc[1], et);
    __syncthreads();

    float fro = sqrtf(sAcc[2]);
    float dd = ssv / fro - ((cc == kk) ? 0.25f : 0.f);
    float dsq = warpSum(dd * dd);
    if (lane == 0) atomicAdd(&sAcc[3], dsq);
    __syncthreads();

    if (t == 0) {
        float m = sAcc[0] * 0.5f;
        float wsq = 0.f, cs2 = 0.f;
        #pragma unroll
        for (int c = 0; c < CC; c++) { wsq += wsh[c] * wsh[c]; cs2 += csh[c] * csh[c]; }
        float trace = sAcc[1] - wsq / (2.f * m);
        float spec = -trace / (2.f * m);
        float ortho = sqrtf(sAcc[3]);
        float cluster = sqrtf(cs2) / (float)NN * 4.f - 1.f;
        atomicAdd(out, (spec + ortho + cluster) * (1.f / (float)BB));
    }
}

// ---------------- launch ----------------
extern "C" void kernel_launch(void* const* d_in, const int* in_sizes, int n_in,
                              void* d_out, int out_size) {
    const int*   x      = (const int*)d_in[0];
    const int*   ei     = (const int*)d_in[1];
    const float* emb    = (const float*)d_in[3];
    const float* w1     = (const float*)d_in[4];
    const float* b1     = (const float*)d_in[5];
    const float* bn_g   = (const float*)d_in[6];
    const float* bn_b   = (const float*)d_in[7];
    const float* bn_m   = (const float*)d_in[8];
    const float* bn_v   = (const float*)d_in[9];
    const float* w2     = (const float*)d_in[10];
    const float* b2     = (const float*)d_in[11];
    const float* pool_w = (const float*)d_in[12];
    const float* pool_b = (const float*)d_in[13];
    float* out = (float*)d_out;

    cudaFuncSetAttribute(gemm_mma<0>, cudaFuncAttributeMaxDynamicSharedMemorySize, SMEM_GEMM);
    cudaFuncSetAttribute(gemm_mma<1>, cudaFuncAttributeMaxDynamicSharedMemorySize, SMEM_GEMM);

    init_kernel<<<(MROWS + 255) / 256, 256>>>(out);
    econv_kernel<<<VOCAB * HD / 512, 256>>>(emb);
    count_kernel<<<ETOT / 256, 256>>>(ei);
    scan_kernel<<<1, 1024>>>();
    fill_kernel<<<ETOT / 256, 256>>>(ei);
    wprep_kernel<<<HD * HD / 256, 256>>>(w1, w2);
    z0_kernel<<<MROWS, 128>>>(x);

    dim3 gGrid(HD / 128, MROWS / 128);   // (4, 256)
    gemm_mma<0><<<gGrid, 256, SMEM_GEMM>>>(b1, bn_g, bn_b, bn_m, bn_v, nullptr);
    gemm_mma<1><<<gGrid, 256, SMEM_GEMM>>>(b2, nullptr, nullptr, nullptr, nullptr, pool_w);

    softmax_kernel<<<MROWS / 256, 256>>>(pool_b);
    loss_kernel<<<BB, 256>>>(ei, out);
}

// round 8
// speedup vs baseline: 3.7512x; 1.1432x over previous
#include <cuda_runtime.h>
#include <cuda_fp16.h>
#include <math.h>
#include <stdint.h>

// Problem constants
#define BB    64
#define NN    512
#define MROWS (BB*NN)        // 32768 nodes
#define DEG   8
#define ETOT  (MROWS*DEG)    // 262144 edges
#define EB    (NN*DEG)       // 4096 edges per batch
#define HD    512            // D == H == 512
#define CC    16
#define VOCAB 10000
#define MAXD  64             // max in-degree capacity (Poisson(8); P(>=64) ~ 1e-40)
#define BN_EPS 1e-5f

// ---------------- static scratch ----------------
__device__ __align__(1024) __half g_E16[VOCAB*HD];          // emb fp16
__device__ __align__(1024) __half g_A16[MROWS*HD];          // z0 fp16
__device__ __align__(1024) __half g_B16[MROWS*HD];          // z1 fp16
__device__ __align__(1024) __half g_W1[HD*HD];              // [n][k] fp16
__device__ __align__(1024) __half g_W2[HD*HD];
__device__ __align__(1024) float  g_logits[MROWS*CC];       // pre-softmax pool logits
__device__ float g_s[MROWS*CC];
__device__ int   g_deg[MROWS];                              // out-degree (adj.sum(-1))
__device__ int   g_cnt[MROWS];                              // in-degree cursor
__device__ int   g_slots[MROWS*MAXD];                       // src lists per dst (8 MB)

__device__ __forceinline__ float warpSum(float v) {
    #pragma unroll
    for (int o = 16; o; o >>= 1) v += __shfl_xor_sync(0xffffffffu, v, o);
    return v;
}

// ---------------- PTX helpers (sm_80+ portable) ----------------
__device__ __forceinline__ uint32_t smem_u32(const void* p) {
    uint32_t a;
    asm("{ .reg .u64 t; cvta.to.shared.u64 t, %1; cvt.u32.u64 %0, t; }" : "=r"(a) : "l"(p));
    return a;
}
__device__ __forceinline__ void cp16(uint32_t dst, const void* src) {
    asm volatile("cp.async.cg.shared.global [%0], [%1], 16;\n" :: "r"(dst), "l"(src));
}
__device__ __forceinline__ void cp_commit() {
    asm volatile("cp.async.commit_group;\n" ::: "memory");
}
template<int N>
__device__ __forceinline__ void cp_wait() {
    asm volatile("cp.async.wait_group %0;\n" :: "n"(N) : "memory");
}
__device__ __forceinline__ void ldm_x4(uint32_t* r, uint32_t addr) {
    asm volatile("ldmatrix.sync.aligned.m8n8.x4.shared.b16 {%0,%1,%2,%3}, [%4];"
                 : "=r"(r[0]), "=r"(r[1]), "=r"(r[2]), "=r"(r[3]) : "r"(addr));
}
__device__ __forceinline__ void mma16816(float* d, const uint32_t* a, const uint32_t* b) {
    asm volatile("mma.sync.aligned.m16n8k16.row.col.f32.f16.f16.f32 "
                 "{%0,%1,%2,%3}, {%4,%5,%6,%7}, {%8,%9}, {%0,%1,%2,%3};"
                 : "+f"(d[0]), "+f"(d[1]), "+f"(d[2]), "+f"(d[3])
                 : "r"(a[0]), "r"(a[1]), "r"(a[2]), "r"(a[3]), "r"(b[0]), "r"(b[1]));
}

// ---------------- init: zero counters, logits, output ----------------
__global__ void init_kernel(float* out) {
    int i = blockIdx.x * blockDim.x + threadIdx.x;
    if (i < MROWS) {
        g_cnt[i] = 0; g_deg[i] = 0;
        float4 z = make_float4(0.f, 0.f, 0.f, 0.f);
        float4* lg = (float4*)(g_logits + i * CC);
        lg[0] = z; lg[1] = z; lg[2] = z; lg[3] = z;
    }
    if (i == 0) out[0] = 0.f;
}

// ---------------- prep: emb->fp16 and W transpose+fp16, one kernel ----------------
// grid covers max(VOCAB*HD/2, HD*HD) indices
__global__ void prep_kernel(const float* __restrict__ emb,
                            const float* __restrict__ w1, const float* __restrict__ w2) {
    int i = blockIdx.x * blockDim.x + threadIdx.x;
    if (i < VOCAB * HD / 2) {
        float2 v = ((const float2*)emb)[i];
        ((__half2*)g_E16)[i] = __floats2half2_rn(v.x, v.y);
    }
    if (i < HD * HD) {       // i = k*512 + n
        int k = i >> 9, n = i & 511;
        g_W1[n * HD + k] = __float2half_rn(w1[i]);
        g_W2[n * HD + k] = __float2half_rn(w2[i]);
    }
}

// ---------------- single-pass edge processing: slots + degrees ----------------
__global__ void edge_kernel(const int* __restrict__ ei) {
    int e = blockIdx.x * blockDim.x + threadIdx.x;
    if (e < ETOT) {
        int s = ei[e];
        int d = ei[ETOT + e];
        int p = atomicAdd(&g_cnt[d], 1);
        if (p < MAXD) g_slots[d * MAXD + p] = s;
        atomicAdd(&g_deg[s], 1);
    }
}

// ---------------- z0 = emb16[x] + segment_sum(emb16[x[src]], dst), fp16 out ----------------
__global__ void z0_kernel(const int* __restrict__ x) {
    int n = blockIdx.x;
    int t = threadIdx.x;  // 128 threads; 4 halves (8B) each
    const uint2* emb2 = (const uint2*)g_E16;   // 4 halves per uint2, 128 per row
    uint2 hv = emb2[(size_t)x[n] * 128 + t];
    float2 a0 = __half22float2(*(__half2*)&hv.x);
    float2 a1 = __half22float2(*(__half2*)&hv.y);
    int cnt = min(g_cnt[n], MAXD);
    const int* slots = g_slots + n * MAXD;
    for (int e = 0; e < cnt; e++) {
        int sx = x[slots[e]];
        uint2 v = emb2[(size_t)sx * 128 + t];
        float2 b0 = __half22float2(*(__half2*)&v.x);
        float2 b1 = __half22float2(*(__half2*)&v.y);
        a0.x += b0.x; a0.y += b0.y; a1.x += b1.x; a1.y += b1.y;
    }
    uint2 out;
    *(__half2*)&out.x = __floats2half2_rn(a0.x, a0.y);
    *(__half2*)&out.y = __floats2half2_rn(a1.x, a1.y);
    ((uint2*)g_A16)[(size_t)n * 128 + t] = out;
}

// ---------------- mma.sync fp16 GEMM ----------------
// 128x128 CTA tile, 8 warps (2x4), K-chunk 64, 3-stage cp.async pipeline, 2 CTAs/SM.
// WHICH==0: z1 = elu(bn(z0 @ w1 + b1)) -> g_B16 (fp16)
// WHICH==1: z2 = elu(z1 @ w2 + b2), fused pool: atomicAdd partial z2@pool_w logits

#define STAGE_BYTES 32768          // A 16K | W 16K
#define NSTAGE 3
#define SMEM_GEMM (NSTAGE * STAGE_BYTES)   // 96 KB

template<int WHICH>
__global__ __launch_bounds__(256, 2) void gemm_mma(
    const float* __restrict__ bias, const float* __restrict__ gamma,
    const float* __restrict__ beta, const float* __restrict__ mean,
    const float* __restrict__ var, const float* __restrict__ poolw)
{
    extern __shared__ __align__(1024) char smem[];
    const uint32_t sb = smem_u32(smem);
    const int tid = threadIdx.x;
    const int wid = tid >> 5, lane = tid & 31;
    const int wm = wid & 1;        // 0..1 -> 64 rows
    const int wn = wid >> 1;       // 0..3 -> 32 cols
    const int rowBase = blockIdx.y * 128;
    const int colBase = blockIdx.x * 128;

    const __half* __restrict__ Ap = WHICH ? g_B16 : g_A16;
    const __half* __restrict__ Wp = WHICH ? g_W2 : g_W1;

    // ---- loader: 8 x 16B cp.async per thread per chunk ----
    auto loadChunk = [&](int c, int s) {
        const uint32_t stage = sb + s * STAGE_BYTES;
        #pragma unroll
        for (int it = 0; it < 8; it++) {
            int idx = tid + it * 256;
            int q = idx >> 10;                    // 0=A, 1=W
            int r = (idx & 1023) >> 3;
            int cc = idx & 7;
            const __half* base = q ? Wp : Ap;
            int grow = (q ? colBase : rowBase) + r;
            const __half* src = base + (size_t)grow * HD + c * 64 + cc * 8;
            uint32_t off = r * 128 + cc * 16;
            uint32_t sw = off ^ ((off >> 3) & 0x70);
            cp16(stage + q * 16384 + sw, src);
        }
        cp_commit();
    };

    // ---- ldmatrix per-thread addressing ----
    const int g = lane >> 3;                  // 0..3
    const int aRowL = (g & 1) * 8 + (lane & 7);
    const int aKb   = (g >> 1);
    const int bRowL = (g >> 1) * 8 + (lane & 7);
    const int bKb   = (g & 1);

    uint32_t aRowOff[4], aXor[4];
    #pragma unroll
    for (int i = 0; i < 4; i++) {
        int ar = wm * 64 + i * 16 + aRowL;
        aRowOff[i] = ar * 128;
        aXor[i] = (ar & 7) << 4;
    }
    uint32_t bRowOff[2], bXor[2];
    #pragma unroll
    for (int p = 0; p < 2; p++) {
        int br = wn * 32 + p * 16 + bRowL;
        bRowOff[p] = br * 128;
        bXor[p] = (br & 7) << 4;
    }

    float acc[4][4][4] = {};

    loadChunk(0, 0);
    loadChunk(1, 1);

    for (int c = 0; c < 8; c++) {
        if (c < 7) cp_wait<1>(); else cp_wait<0>();
        __syncthreads();
        if (c + 2 < 8) loadChunk(c + 2, (c + 2) % NSTAGE);

        const uint32_t stage = sb + (c % NSTAGE) * STAGE_BYTES;
        const uint32_t aPl = stage, bPl = stage + 16384;

        #pragma unroll
        for (int s = 0; s < 4; s++) {          // k16 steps within 64-chunk
            uint32_t ah[4][4], bh[2][4];
            uint32_t aCol = (uint32_t)(s * 32 + aKb * 16);
            uint32_t bCol = (uint32_t)(s * 32 + bKb * 16);
            #pragma unroll
            for (int i = 0; i < 4; i++)
                ldm_x4(ah[i], aPl + aRowOff[i] + (aCol ^ aXor[i]));
            #pragma unroll
            for (int p = 0; p < 2; p++)
                ldm_x4(bh[p], bPl + bRowOff[p] + (bCol ^ bXor[p]));
            #pragma unroll
            for (int i = 0; i < 4; i++)
                #pragma unroll
                for (int j = 0; j < 4; j++)
                    mma16816(acc[i][j], ah[i], &bh[j >> 1][(j & 1) * 2]);
        }
        __syncthreads();
    }
    __syncthreads();   // final chunk's stage overlaps epilogue smem reuse

    // ---- epilogue ----
    const int rlane = lane >> 2;
    const int clane = (lane & 3) * 2;
    float* sE = (float*)smem;                 // [128][129] for WHICH==1

    #pragma unroll
    for (int i = 0; i < 4; i++) {
        int rl0 = wm * 64 + i * 16 + rlane;
        #pragma unroll
        for (int j = 0; j < 4; j++) {
            int cl = wn * 32 + j * 8 + clane;
            int col = colBase + cl;
            float b0 = bias[col], b1v = bias[col + 1];
            float s0 = 1.f, s1 = 1.f, o0 = 0.f, o1 = 0.f;
            if (WHICH == 0) {
                s0 = rsqrtf(var[col] + BN_EPS) * gamma[col];
                s1 = rsqrtf(var[col + 1] + BN_EPS) * gamma[col + 1];
                o0 = beta[col] - mean[col] * s0;
                o1 = beta[col + 1] - mean[col + 1] * s1;
            }
            #pragma unroll
            for (int h = 0; h < 2; h++) {
                int rl = rl0 + h * 8;
                float v0 = acc[i][j][h * 2 + 0] + b0;
                float v1 = acc[i][j][h * 2 + 1] + b1v;
                if (WHICH == 0) { v0 = v0 * s0 + o0; v1 = v1 * s1 + o1; }
                v0 = v0 > 0.f ? v0 : expm1f(v0);
                v1 = v1 > 0.f ? v1 : expm1f(v1);
                if (WHICH == 0) {
                    *(__half2*)(g_B16 + (size_t)(rowBase + rl) * HD + col) =
                        __floats2half2_rn(v0, v1);
                } else {
                    sE[rl * 129 + cl] = v0;
                    sE[rl * 129 + cl + 1] = v1;
                }
            }
        }
    }

    if (WHICH == 1) {
        // fused pool: partial logits = sE(128x128) @ pool_w[colBase:colBase+128, 0:16]
        float* sPw = sE + 128 * 129;          // [128][16] = 8 KB
        __syncthreads();
        #pragma unroll
        for (int jj = 0; jj < 8; jj++) {
            int idx = tid * 8 + jj;
            int k = idx >> 4, cch = idx & 15;
            sPw[k * 16 + cch] = poolw[(size_t)(colBase + k) * CC + cch];
        }
        __syncthreads();
        int r = tid & 127;
        int c0 = (tid >> 7) * 8;
        float a8[8] = {};
        #pragma unroll 4
        for (int k = 0; k < 128; k++) {
            float zv = sE[r * 129 + k];
            #pragma unroll
            for (int c8 = 0; c8 < 8; c8++) a8[c8] += zv * sPw[k * 16 + c0 + c8];
        }
        float* dst = g_logits + (size_t)(rowBase + r) * CC + c0;
        #pragma unroll
        for (int c8 = 0; c8 < 8; c8++) atomicAdd(dst + c8, a8[c8]);
    }
}

// ---------------- softmax: s = softmax(logits + pool_b) ----------------
__global__ __launch_bounds__(256) void softmax_kernel(const float* __restrict__ pb) {
    int n = blockIdx.x * blockDim.x + threadIdx.x;
    float l[CC];
    const float4* src = (const float4*)(g_logits + (size_t)n * CC);
    #pragma unroll
    for (int q = 0; q < 4; q++) ((float4*)l)[q] = src[q];
    float mx = -INFINITY;
    #pragma unroll
    for (int c = 0; c < CC; c++) { l[c] += pb[c]; mx = fmaxf(mx, l[c]); }
    float sum = 0.f;
    #pragma unroll
    for (int c = 0; c < CC; c++) { l[c] = expf(l[c] - mx); sum += l[c]; }
    float inv = 1.f / sum;
    float4* dst = (float4*)(g_s + (size_t)n * CC);
    #pragma unroll
    for (int c = 0; c < CC; c++) l[c] *= inv;
    #pragma unroll
    for (int q = 0; q < 4; q++) dst[q] = ((float4*)l)[q];
}

// ---------------- per-batch losses ----------------
__global__ __launch_bounds__(256) void loss_kernel(const int* __restrict__ ei,
                                                   float* __restrict__ out) {
    __shared__ float ssh[NN * CC];
    __shared__ float dsh[NN];
    __shared__ float wsh[CC], csh[CC];
    __shared__ float sAcc[4];
    int b = blockIdx.x, t = threadIdx.x;
    int lane = t & 31;

    for (int i = t; i < NN * CC; i += 256) ssh[i] = g_s[b * NN * CC + i];
    for (int i = t; i < NN; i += 256) dsh[i] = (float)g_deg[b * NN + i];
    if (t < CC) { wsh[t] = 0.f; csh[t] = 0.f; }
    if (t < 4) sAcc[t] = 0.f;
    __syncthreads();

    float wp[CC] = {}, cp[CC] = {};
    float td = 0.f;
    for (int n = t; n < NN; n += 256) {
        float d = dsh[n];
        td += d;
        #pragma unroll
        for (int c = 0; c < CC; c++) {
            float sv = ssh[n * CC + c];
            wp[c] += sv * d;
            cp[c] += sv;
        }
    }
    td = warpSum(td);
    #pragma unroll
    for (int c = 0; c < CC; c++) { wp[c] = warpSum(wp[c]); cp[c] = warpSum(cp[c]); }
    if (lane == 0) {
        atomicAdd(&sAcc[0], td);
        #pragma unroll
        for (int c = 0; c < CC; c++) { atomicAdd(&wsh[c], wp[c]); atomicAdd(&csh[c], cp[c]); }
    }

    int cc = t >> 4, kk = t & 15;
    float ssv = 0.f;
    for (int n = 0; n < NN; n++) ssv += ssh[n * CC + cc] * ssh[n * CC + kk];
    float s2 = warpSum(ssv * ssv);
    if (lane == 0) atomicAdd(&sAcc[2], s2);

    const int* srcp = ei;
    const int* dstp = ei + ETOT;
    float et = 0.f;
    for (int e = b * EB + t; e < (b + 1) * EB; e += 256) {
        int sl = srcp[e] - b * NN;
        int dl = dstp[e] - b * NN;
        float d2 = 0.f;
        #pragma unroll
        for (int c = 0; c < CC; c++) d2 += ssh[sl * CC + c] * ssh[dl * CC + c];
        et += d2;
    }
    et = warpSum(et);
    if (lane == 0) atomicAdd(&sAcc[1], et);
    __syncthreads();

    float fro = sqrtf(sAcc[2]);
    float dd = ssv / fro - ((cc == kk) ? 0.25f : 0.f);
    float dsq = warpSum(dd * dd);
    if (lane == 0) atomicAdd(&sAcc[3], dsq);
    __syncthreads();

    if (t == 0) {
        float m = sAcc[0] * 0.5f;
        float wsq = 0.f, cs2 = 0.f;
        #pragma unroll
        for (int c = 0; c < CC; c++) { wsq += wsh[c] * wsh[c]; cs2 += csh[c] * csh[c]; }
        float trace = sAcc[1] - wsq / (2.f * m);
        float spec = -trace / (2.f * m);
        float ortho = sqrtf(sAcc[3]);
        float cluster = sqrtf(cs2) / (float)NN * 4.f - 1.f;
        atomicAdd(out, (spec + ortho + cluster) * (1.f / (float)BB));
    }
}

// ---------------- launch ----------------
extern "C" void kernel_launch(void* const* d_in, const int* in_sizes, int n_in,
                              void* d_out, int out_size) {
    const int*   x      = (const int*)d_in[0];
    const int*   ei     = (const int*)d_in[1];
    const float* emb    = (const float*)d_in[3];
    const float* w1     = (const float*)d_in[4];
    const float* b1     = (const float*)d_in[5];
    const float* bn_g   = (const float*)d_in[6];
    const float* bn_b   = (const float*)d_in[7];
    const float* bn_m   = (const float*)d_in[8];
    const float* bn_v   = (const float*)d_in[9];
    const float* w2     = (const float*)d_in[10];
    const float* b2     = (const float*)d_in[11];
    const float* pool_w = (const float*)d_in[12];
    const float* pool_b = (const float*)d_in[13];
    float* out = (float*)d_out;

    cudaFuncSetAttribute(gemm_mma<0>, cudaFuncAttributeMaxDynamicSharedMemorySize, SMEM_GEMM);
    cudaFuncSetAttribute(gemm_mma<1>, cudaFuncAttributeMaxDynamicSharedMemorySize, SMEM_GEMM);

    init_kernel<<<(MROWS + 255) / 256, 256>>>(out);
    prep_kernel<<<(VOCAB * HD / 2 + 255) / 256, 256>>>(emb, w1, w2);
    edge_kernel<<<ETOT / 256, 256>>>(ei);
    z0_kernel<<<MROWS, 128>>>(x);

    dim3 gGrid(HD / 128, MROWS / 128);   // (4, 256)
    gemm_mma<0><<<gGrid, 256, SMEM_GEMM>>>(b1, bn_g, bn_b, bn_m, bn_v, nullptr);
    gemm_mma<1><<<gGrid, 256, SMEM_GEMM>>>(b2, nullptr, nullptr, nullptr, nullptr, pool_w);

    softmax_kernel<<<MROWS / 256, 256>>>(pool_b);
    loss_kernel<<<BB, 256>>>(ei, out);
}

// round 9
// speedup vs baseline: 3.9715x; 1.0587x over previous
#include <cuda_runtime.h>
#include <cuda_fp16.h>
#include <math.h>
#include <stdint.h>

// Problem constants
#define BB    64
#define NN    512
#define MROWS (BB*NN)        // 32768 nodes
#define DEG   8
#define ETOT  (MROWS*DEG)    // 262144 edges
#define EB    (NN*DEG)       // 4096 edges per batch
#define HD    512            // D == H == 512
#define CC    16
#define VOCAB 10000
#define MAXD  64             // max in-degree capacity (Poisson(8); P(>=64) ~ 1e-40)
#define BN_EPS 1e-5f

// ---------------- static scratch ----------------
__device__ __align__(1024) __half g_E16[VOCAB*HD];          // emb fp16
__device__ __align__(1024) __half g_A16[MROWS*HD];          // z0 fp16
__device__ __align__(1024) __half g_B16[MROWS*HD];          // z1 fp16
__device__ __align__(1024) __half g_W1[HD*HD];              // [n][k] fp16
__device__ __align__(1024) __half g_W2[HD*HD];
__device__ __align__(1024) float  g_logits[MROWS*CC];       // pre-softmax pool logits
__device__ int   g_deg[MROWS];                              // out-degree (adj.sum(-1))
__device__ int   g_cnt[MROWS];                              // in-degree cursor
__device__ int   g_slots[MROWS*MAXD];                       // src lists per dst (8 MB)

__device__ __forceinline__ float warpSum(float v) {
    #pragma unroll
    for (int o = 16; o; o >>= 1) v += __shfl_xor_sync(0xffffffffu, v, o);
    return v;
}

// ---------------- PTX helpers (sm_80+ portable) ----------------
__device__ __forceinline__ uint32_t smem_u32(const void* p) {
    uint32_t a;
    asm("{ .reg .u64 t; cvta.to.shared.u64 t, %1; cvt.u32.u64 %0, t; }" : "=r"(a) : "l"(p));
    return a;
}
__device__ __forceinline__ void cp16(uint32_t dst, const void* src) {
    asm volatile("cp.async.cg.shared.global [%0], [%1], 16;\n" :: "r"(dst), "l"(src));
}
__device__ __forceinline__ void cp_commit() {
    asm volatile("cp.async.commit_group;\n" ::: "memory");
}
template<int N>
__device__ __forceinline__ void cp_wait() {
    asm volatile("cp.async.wait_group %0;\n" :: "n"(N) : "memory");
}
__device__ __forceinline__ void ldm_x4(uint32_t* r, uint32_t addr) {
    asm volatile("ldmatrix.sync.aligned.m8n8.x4.shared.b16 {%0,%1,%2,%3}, [%4];"
                 : "=r"(r[0]), "=r"(r[1]), "=r"(r[2]), "=r"(r[3]) : "r"(addr));
}
__device__ __forceinline__ void mma16816(float* d, const uint32_t* a, const uint32_t* b) {
    asm volatile("mma.sync.aligned.m16n8k16.row.col.f32.f16.f16.f32 "
                 "{%0,%1,%2,%3}, {%4,%5,%6,%7}, {%8,%9}, {%0,%1,%2,%3};"
                 : "+f"(d[0]), "+f"(d[1]), "+f"(d[2]), "+f"(d[3])
                 : "r"(a[0]), "r"(a[1]), "r"(a[2]), "r"(a[3]), "r"(b[0]), "r"(b[1]));
}

// ---------------- prep: init counters/logits/out + emb->fp16 + W transpose ----------------
__global__ void prep_kernel(const float* __restrict__ emb,
                            const float* __restrict__ w1, const float* __restrict__ w2,
                            float* out) {
    int i = blockIdx.x * blockDim.x + threadIdx.x;
    if (i < MROWS) {
        g_cnt[i] = 0; g_deg[i] = 0;
        float4 z = make_float4(0.f, 0.f, 0.f, 0.f);
        float4* lg = (float4*)(g_logits + i * CC);
        lg[0] = z; lg[1] = z; lg[2] = z; lg[3] = z;
    }
    if (i < VOCAB * HD / 2) {
        float2 v = ((const float2*)emb)[i];
        ((__half2*)g_E16)[i] = __floats2half2_rn(v.x, v.y);
    }
    if (i < HD * HD) {       // i = k*512 + n
        int k = i >> 9, n = i & 511;
        g_W1[n * HD + k] = __float2half_rn(w1[i]);
        g_W2[n * HD + k] = __float2half_rn(w2[i]);
    }
    if (i == 0) out[0] = 0.f;
}

// ---------------- single-pass edge processing: slots + degrees ----------------
__global__ void edge_kernel(const int* __restrict__ ei) {
    int e = blockIdx.x * blockDim.x + threadIdx.x;
    if (e < ETOT) {
        int s = ei[e];
        int d = ei[ETOT + e];
        int p = atomicAdd(&g_cnt[d], 1);
        if (p < MAXD) g_slots[d * MAXD + p] = s;
        atomicAdd(&g_deg[s], 1);
    }
}

// ---------------- z0 = emb16[x] + segment_sum(emb16[x[src]], dst), fp16 ----------------
// 4 nodes per block; 64 threads per node, uint4 (8 halves) each; hadd2 accumulation;
// neighbor token indices prefetched to shared once per node.
__global__ __launch_bounds__(256) void z0_kernel(const int* __restrict__ x) {
    __shared__ int s_sx[4][MAXD];
    __shared__ int s_meta[4][2];       // [cnt, self_token]
    int t = threadIdx.x;
    int sub = t >> 6, lane = t & 63;
    int n = blockIdx.x * 4 + sub;
    int cnt = min(g_cnt[n], MAXD);
    if (lane == 0) { s_meta[sub][0] = cnt; s_meta[sub][1] = x[n]; }
    if (lane < cnt) s_sx[sub][lane] = x[g_slots[n * MAXD + lane]];
    __syncthreads();

    const uint4* emb4 = (const uint4*)g_E16;   // 8 halves per uint4, 64 per row
    cnt = s_meta[sub][0];
    uint4 hv = emb4[(size_t)s_meta[sub][1] * 64 + lane];
    __half2 a0 = *(__half2*)&hv.x, a1 = *(__half2*)&hv.y;
    __half2 a2 = *(__half2*)&hv.z, a3 = *(__half2*)&hv.w;
    for (int e = 0; e < cnt; e++) {
        uint4 v = emb4[(size_t)s_sx[sub][e] * 64 + lane];
        a0 = __hadd2(a0, *(__half2*)&v.x);
        a1 = __hadd2(a1, *(__half2*)&v.y);
        a2 = __hadd2(a2, *(__half2*)&v.z);
        a3 = __hadd2(a3, *(__half2*)&v.w);
    }
    uint4 outv;
    *(__half2*)&outv.x = a0; *(__half2*)&outv.y = a1;
    *(__half2*)&outv.z = a2; *(__half2*)&outv.w = a3;
    ((uint4*)g_A16)[(size_t)n * 64 + lane] = outv;
}

// ---------------- mma.sync fp16 GEMM ----------------
// 128x128 CTA tile, 8 warps (2x4), K-chunk 64, 3-stage cp.async pipeline, 2 CTAs/SM.
// WHICH==0: z1 = elu(bn(z0 @ w1 + b1)) -> g_B16 (fp16)
// WHICH==1: z2 = elu(z1 @ w2 + b2), fused pool: atomicAdd partial z2@pool_w logits

#define STAGE_BYTES 32768          // A 16K | W 16K
#define NSTAGE 3
#define SMEM_GEMM (NSTAGE * STAGE_BYTES)   // 96 KB

template<int WHICH>
__global__ __launch_bounds__(256, 2) void gemm_mma(
    const float* __restrict__ bias, const float* __restrict__ gamma,
    const float* __restrict__ beta, const float* __restrict__ mean,
    const float* __restrict__ var, const float* __restrict__ poolw)
{
    extern __shared__ __align__(1024) char smem[];
    const uint32_t sb = smem_u32(smem);
    const int tid = threadIdx.x;
    const int wid = tid >> 5, lane = tid & 31;
    const int wm = wid & 1;        // 0..1 -> 64 rows
    const int wn = wid >> 1;       // 0..3 -> 32 cols
    const int rowBase = blockIdx.y * 128;
    const int colBase = blockIdx.x * 128;

    const __half* __restrict__ Ap = WHICH ? g_B16 : g_A16;
    const __half* __restrict__ Wp = WHICH ? g_W2 : g_W1;

    // ---- loader: 8 x 16B cp.async per thread per chunk ----
    auto loadChunk = [&](int c, int s) {
        const uint32_t stage = sb + s * STAGE_BYTES;
        #pragma unroll
        for (int it = 0; it < 8; it++) {
            int idx = tid + it * 256;
            int q = idx >> 10;                    // 0=A, 1=W
            int r = (idx & 1023) >> 3;
            int cc = idx & 7;
            const __half* base = q ? Wp : Ap;
            int grow = (q ? colBase : rowBase) + r;
            const __half* src = base + (size_t)grow * HD + c * 64 + cc * 8;
            uint32_t off = r * 128 + cc * 16;
            uint32_t sw = off ^ ((off >> 3) & 0x70);
            cp16(stage + q * 16384 + sw, src);
        }
        cp_commit();
    };

    // ---- ldmatrix per-thread addressing ----
    const int g = lane >> 3;                  // 0..3
    const int aRowL = (g & 1) * 8 + (lane & 7);
    const int aKb   = (g >> 1);
    const int bRowL = (g >> 1) * 8 + (lane & 7);
    const int bKb   = (g & 1);

    uint32_t aRowOff[4], aXor[4];
    #pragma unroll
    for (int i = 0; i < 4; i++) {
        int ar = wm * 64 + i * 16 + aRowL;
        aRowOff[i] = ar * 128;
        aXor[i] = (ar & 7) << 4;
    }
    uint32_t bRowOff[2], bXor[2];
    #pragma unroll
    for (int p = 0; p < 2; p++) {
        int br = wn * 32 + p * 16 + bRowL;
        bRowOff[p] = br * 128;
        bXor[p] = (br & 7) << 4;
    }

    float acc[4][4][4] = {};

    loadChunk(0, 0);
    loadChunk(1, 1);

    for (int c = 0; c < 8; c++) {
        if (c < 7) cp_wait<1>(); else cp_wait<0>();
        __syncthreads();
        if (c + 2 < 8) loadChunk(c + 2, (c + 2) % NSTAGE);

        const uint32_t stage = sb + (c % NSTAGE) * STAGE_BYTES;
        const uint32_t aPl = stage, bPl = stage + 16384;

        #pragma unroll
        for (int s = 0; s < 4; s++) {          // k16 steps within 64-chunk
            uint32_t ah[4][4], bh[2][4];
            uint32_t aCol = (uint32_t)(s * 32 + aKb * 16);
            uint32_t bCol = (uint32_t)(s * 32 + bKb * 16);
            #pragma unroll
            for (int i = 0; i < 4; i++)
                ldm_x4(ah[i], aPl + aRowOff[i] + (aCol ^ aXor[i]));
            #pragma unroll
            for (int p = 0; p < 2; p++)
                ldm_x4(bh[p], bPl + bRowOff[p] + (bCol ^ bXor[p]));
            #pragma unroll
            for (int i = 0; i < 4; i++)
                #pragma unroll
                for (int j = 0; j < 4; j++)
                    mma16816(acc[i][j], ah[i], &bh[j >> 1][(j & 1) * 2]);
        }
        __syncthreads();
    }
    __syncthreads();   // final chunk's stage overlaps epilogue smem reuse

    // ---- epilogue ----
    const int rlane = lane >> 2;
    const int clane = (lane & 3) * 2;
    float* sE = (float*)smem;                 // [128][129] for WHICH==1

    #pragma unroll
    for (int i = 0; i < 4; i++) {
        int rl0 = wm * 64 + i * 16 + rlane;
        #pragma unroll
        for (int j = 0; j < 4; j++) {
            int cl = wn * 32 + j * 8 + clane;
            int col = colBase + cl;
            float b0 = bias[col], b1v = bias[col + 1];
            float s0 = 1.f, s1 = 1.f, o0 = 0.f, o1 = 0.f;
            if (WHICH == 0) {
                s0 = rsqrtf(var[col] + BN_EPS) * gamma[col];
                s1 = rsqrtf(var[col + 1] + BN_EPS) * gamma[col + 1];
                o0 = beta[col] - mean[col] * s0;
                o1 = beta[col + 1] - mean[col + 1] * s1;
            }
            #pragma unroll
            for (int h = 0; h < 2; h++) {
                int rl = rl0 + h * 8;
                float v0 = acc[i][j][h * 2 + 0] + b0;
                float v1 = acc[i][j][h * 2 + 1] + b1v;
                if (WHICH == 0) { v0 = v0 * s0 + o0; v1 = v1 * s1 + o1; }
                v0 = v0 > 0.f ? v0 : expm1f(v0);
                v1 = v1 > 0.f ? v1 : expm1f(v1);
                if (WHICH == 0) {
                    *(__half2*)(g_B16 + (size_t)(rowBase + rl) * HD + col) =
                        __floats2half2_rn(v0, v1);
                } else {
                    sE[rl * 129 + cl] = v0;
                    sE[rl * 129 + cl + 1] = v1;
                }
            }
        }
    }

    if (WHICH == 1) {
        // fused pool: partial logits = sE(128x128) @ pool_w[colBase:colBase+128, 0:16]
        float* sPw = sE + 128 * 129;          // [128][16] = 8 KB
        __syncthreads();
        #pragma unroll
        for (int jj = 0; jj < 8; jj++) {
            int idx = tid * 8 + jj;
            int k = idx >> 4, cch = idx & 15;
            sPw[k * 16 + cch] = poolw[(size_t)(colBase + k) * CC + cch];
        }
        __syncthreads();
        int r = tid & 127;
        int c0 = (tid >> 7) * 8;
        float a8[8] = {};
        #pragma unroll 4
        for (int k = 0; k < 128; k++) {
            float zv = sE[r * 129 + k];
            #pragma unroll
            for (int c8 = 0; c8 < 8; c8++) a8[c8] += zv * sPw[k * 16 + c0 + c8];
        }
        float* dst = g_logits + (size_t)(rowBase + r) * CC + c0;
        #pragma unroll
        for (int c8 = 0; c8 < 8; c8++) atomicAdd(dst + c8, a8[c8]);
    }
}

// ---------------- per-batch losses (softmax fused in) ----------------
__global__ __launch_bounds__(256) void loss_kernel(const int* __restrict__ ei,
                                                   const float* __restrict__ pb,
                                                   float* __restrict__ out) {
    __shared__ float ssh[NN * CC];   // logits -> s, in place
    __shared__ float dsh[NN];
    __shared__ float wsh[CC], csh[CC], pbs[CC];
    __shared__ float sAcc[4];
    int b = blockIdx.x, t = threadIdx.x;
    int lane = t & 31;

    for (int i = t; i < NN * CC; i += 256) ssh[i] = g_logits[b * NN * CC + i];
    for (int i = t; i < NN; i += 256) dsh[i] = (float)g_deg[b * NN + i];
    if (t < CC) { wsh[t] = 0.f; csh[t] = 0.f; pbs[t] = pb[t]; }
    if (t < 4) sAcc[t] = 0.f;
    __syncthreads();

    // softmax per node (2 rows per thread), in place
    for (int r = t; r < NN; r += 256) {
        float* row = ssh + r * CC;
        float l[CC];
        float mx = -INFINITY;
        #pragma unroll
        for (int c = 0; c < CC; c++) { l[c] = row[c] + pbs[c]; mx = fmaxf(mx, l[c]); }
        float sum = 0.f;
        #pragma unroll
        for (int c = 0; c < CC; c++) { l[c] = expf(l[c] - mx); sum += l[c]; }
        float inv = 1.f / sum;
        #pragma unroll
        for (int c = 0; c < CC; c++) row[c] = l[c] * inv;
    }
    __syncthreads();

    float wp[CC] = {}, cp[CC] = {};
    float td = 0.f;
    for (int n = t; n < NN; n += 256) {
        float d = dsh[n];
        td += d;
        #pragma unroll
        for (int c = 0; c < CC; c++) {
            float sv = ssh[n * CC + c];
            wp[c] += sv * d;
            cp[c] += sv;
        }
    }
    td = warpSum(td);
    #pragma unroll
    for (int c = 0; c < CC; c++) { wp[c] = warpSum(wp[c]); cp[c] = warpSum(cp[c]); }
    if (lane == 0) {
        atomicAdd(&sAcc[0], td);
        #pragma unroll
        for (int c = 0; c < CC; c++) { atomicAdd(&wsh[c], wp[c]); atomicAdd(&csh[c], cp[c]); }
    }

    int cc = t >> 4, kk = t & 15;
    float ssv = 0.f;
    for (int n = 0; n < NN; n++) ssv += ssh[n * CC + cc] * ssh[n * CC + kk];
    float s2 = warpSum(ssv * ssv);
    if (lane == 0) atomicAdd(&sAcc[2], s2);

    const int* srcp = ei;
    const int* dstp = ei + ETOT;
    float et = 0.f;
    for (int e = b * EB + t; e < (b + 1) * EB; e += 256) {
        int sl = srcp[e] - b * NN;
        int dl = dstp[e] - b * NN;
        float d2 = 0.f;
        #pragma unroll
        for (int c = 0; c < CC; c++) d2 += ssh[sl * CC + c] * ssh[dl * CC + c];
        et += d2;
    }
    et = warpSum(et);
    if (lane == 0) atomicAdd(&sAcc[1], et);
    __syncthreads();

    float fro = sqrtf(sAcc[2]);
    float dd = ssv / fro - ((cc == kk) ? 0.25f : 0.f);
    float dsq = warpSum(dd * dd);
    if (lane == 0) atomicAdd(&sAcc[3], dsq);
    __syncthreads();

    if (t == 0) {
        float m = sAcc[0] * 0.5f;
        float wsq = 0.f, cs2 = 0.f;
        #pragma unroll
        for (int c = 0; c < CC; c++) { wsq += wsh[c] * wsh[c]; cs2 += csh[c] * csh[c]; }
        float trace = sAcc[1] - wsq / (2.f * m);
        float spec = -trace / (2.f * m);
        float ortho = sqrtf(sAcc[3]);
        float cluster = sqrtf(cs2) / (float)NN * 4.f - 1.f;
        atomicAdd(out, (spec + ortho + cluster) * (1.f / (float)BB));
    }
}

// ---------------- launch ----------------
extern "C" void kernel_launch(void* const* d_in, const int* in_sizes, int n_in,
                              void* d_out, int out_size) {
    const int*   x      = (const int*)d_in[0];
    const int*   ei     = (const int*)d_in[1];
    const float* emb    = (const float*)d_in[3];
    const float* w1     = (const float*)d_in[4];
    const float* b1     = (const float*)d_in[5];
    const float* bn_g   = (const float*)d_in[6];
    const float* bn_b   = (const float*)d_in[7];
    const float* bn_m   = (const float*)d_in[8];
    const float* bn_v   = (const float*)d_in[9];
    const float* w2     = (const float*)d_in[10];
    const float* b2     = (const float*)d_in[11];
    const float* pool_w = (const float*)d_in[12];
    const float* pool_b = (const float*)d_in[13];
    float* out = (float*)d_out;

    cudaFuncSetAttribute(gemm_mma<0>, cudaFuncAttributeMaxDynamicSharedMemorySize, SMEM_GEMM);
    cudaFuncSetAttribute(gemm_mma<1>, cudaFuncAttributeMaxDynamicSharedMemorySize, SMEM_GEMM);

    prep_kernel<<<(VOCAB * HD / 2 + 255) / 256, 256>>>(emb, w1, w2, out);
    edge_kernel<<<ETOT / 256, 256>>>(ei);
    z0_kernel<<<MROWS / 4, 256>>>(x);

    dim3 gGrid(HD / 128, MROWS / 128);   // (4, 256)
    gemm_mma<0><<<gGrid, 256, SMEM_GEMM>>>(b1, bn_g, bn_b, bn_m, bn_v, nullptr);
    gemm_mma<1><<<gGrid, 256, SMEM_GEMM>>>(b2, nullptr, nullptr, nullptr, nullptr, pool_w);

    loss_kernel<<<BB, 256>>>(ei, pool_b, out);
}